// round 10
// baseline (speedup 1.0000x reference)
#include <cuda_runtime.h>
#include <cuda_fp16.h>
#include <math.h>
#include <stdint.h>

// Problem constants
#define L_   2
#define P_   3
#define R_   512
#define A_   196
#define V_   9487
#define B_   256
#define BA_  (B_*A_)        // 50176
#define KC_  (2*L_*A_)      // 784
#define G4_  (4*R_)         // 2048

// ---------------------------------------------------------------------------
// Static device scratch (allocation-free)
// ---------------------------------------------------------------------------
__device__ __half gMh   [(size_t)BA_ * KC_];     // logits half (calls 1,3 cols)
__device__ __half g_atth [(size_t)B_ * A_ * R_]; // att in half
__device__ __half g_a2awh[(size_t)KC_ * R_];     // a2a_w in half
__device__ float g_hh2  [2 * B_ * A_];
__device__ float g_hhp  [4 * B_ * A_];           // K-split partials for call1 hh
__device__ float g_score[BA_];
__device__ float g_scorep[4 * BA_];              // fused-score partials
__device__ float g_att0 [2 * B_ * R_];
__device__ float g_sums [P_ * B_ * G4_];
__device__ float g_xt   [B_ * R_];
__device__ float g_nh   [B_ * R_];

// ---------------------------------------------------------------------------
// MUFU-based activations
// ---------------------------------------------------------------------------
__device__ __forceinline__ float mexp(float x) {
    float r;
    asm("ex2.approx.f32 %0, %1;" : "=f"(r) : "f"(x * 1.4426950408889634f));
    return r;
}
__device__ __forceinline__ float msig(float x) {
    float t = fminf(-1.4426950408889634f * x, 126.0f);
    float u;
    asm("ex2.approx.f32 %0, %1;" : "=f"(u) : "f"(t));
    float d = 1.0f + u;
    float r;
    asm("rcp.approx.f32 %0, %1;" : "=f"(r) : "f"(d));
    r = r * fmaf(-d, r, 2.0f);
    return r;
}
__device__ __forceinline__ float mtanh(float x) {
    return fmaf(2.0f, msig(2.0f * x), -1.0f);
}
__device__ __forceinline__ __half2 htanh2(__half2 v) {
    uint32_t vi = *reinterpret_cast<uint32_t*>(&v);
    uint32_t to;
    asm("tanh.approx.f16x2 %0, %1;" : "=r"(to) : "r"(vi));
    return *reinterpret_cast<__half2*>(&to);
}

// ---------------------------------------------------------------------------
// mma / cp.async / ldmatrix helpers
// ---------------------------------------------------------------------------
#define MMA_TF32(c, a, b) \
    asm volatile("mma.sync.aligned.m16n8k8.row.col.f32.tf32.tf32.f32 " \
        "{%0,%1,%2,%3}, {%4,%5,%6,%7}, {%8,%9}, {%0,%1,%2,%3};" \
        : "+f"((c)[0]), "+f"((c)[1]), "+f"((c)[2]), "+f"((c)[3]) \
        : "r"((a)[0]), "r"((a)[1]), "r"((a)[2]), "r"((a)[3]), \
          "r"((b)[0]), "r"((b)[1]))

#define MMA_F16(c, a, b0, b1) \
    asm volatile("mma.sync.aligned.m16n8k16.row.col.f32.f16.f16.f32 " \
        "{%0,%1,%2,%3}, {%4,%5,%6,%7}, {%8,%9}, {%0,%1,%2,%3};" \
        : "+f"((c)[0]), "+f"((c)[1]), "+f"((c)[2]), "+f"((c)[3]) \
        : "r"((a)[0]), "r"((a)[1]), "r"((a)[2]), "r"((a)[3]), \
          "r"(b0), "r"(b1))

#define LDSM_X4(r0, r1, r2, r3, addr) \
    asm volatile("ldmatrix.sync.aligned.m8n8.x4.shared.b16 {%0,%1,%2,%3}, [%4];" \
        : "=r"(r0), "=r"(r1), "=r"(r2), "=r"(r3) : "r"(addr))

__device__ __forceinline__ uint32_t smem_u32(const void* p) {
    uint32_t a;
    asm("{ .reg .u64 t; cvta.to.shared.u64 t, %1; cvt.u32.u64 %0, t; }" : "=r"(a) : "l"(p));
    return a;
}
__device__ __forceinline__ void cp16(uint32_t dst, const void* src) {
    asm volatile("cp.async.cg.shared.global [%0], [%1], 16;" :: "r"(dst), "l"(src));
}
#define CP_COMMIT() asm volatile("cp.async.commit_group;" ::: "memory")
#define CP_WAIT1()  asm volatile("cp.async.wait_group 1;" ::: "memory")

// ---------------------------------------------------------------------------
// Pipelined mma.sync tf32 NT GEMM (unchanged R4 core)
// ---------------------------------------------------------------------------
template<int BN>
__global__ __launch_bounds__(256, 2)
void gemm_mma(const float* __restrict__ A0, const float* __restrict__ A1,
              const float* __restrict__ A2,
              const float* __restrict__ B0, const float* __restrict__ B1,
              const float* __restrict__ B2,
              float* __restrict__ C, const float* __restrict__ bias,
              int N, int Ktot, int ldc,
              long long sA, long long sB, long long sC, long long sBias)
{
    constexpr int NT    = BN / 16;
    constexpr int AW    = 128 * 32;
    constexpr int BW    = BN * 32;
    constexpr int STAGE = AW + BW;

    extern __shared__ float sm[];

    const int tid   = threadIdx.x;
    const int warp  = tid >> 5;
    const int lane  = tid & 31;
    const int gid   = lane >> 2;
    const int tig   = lane & 3;
    const int mbase = (warp & 3) * 32;
    const int nbase = (warp >> 2) * (BN / 2);

    const int row0 = blockIdx.y * 128;
    const int col0 = blockIdx.x * BN;
    const int z    = blockIdx.z;

    const int sr  = tid >> 3;
    const int sc4 = tid & 7;
    const uint32_t smbase = smem_u32(sm);
    const uint32_t swoff  = (uint32_t)((sc4 ^ (sr & 7)) << 2);

    const int ncc = Ktot >> 5;

    auto issue = [&](int cc) {
        if (cc < ncc) {
            const int kb  = cc << 5;
            const int seg = kb >> 9;
            const int kbl = kb & 511;
            const float* Ap = ((seg == 0) ? A0 : (seg == 1) ? A1 : A2)
                              + (long long)z * sA + kbl + sc4 * 4;
            const float* Bp = ((seg == 0) ? B0 : (seg == 1) ? B1 : B2)
                              + (long long)z * sB + kbl + sc4 * 4;
            const uint32_t stA = smbase + (uint32_t)(cc % 3) * (STAGE * 4);
            const uint32_t stB = stA + AW * 4;
            #pragma unroll
            for (int j = 0; j < 4; j++) {
                int r = sr + j * 32;
                cp16(stA + (r * 32) * 4 + swoff * 4,
                     Ap + (long long)(row0 + r) * 512);
            }
            #pragma unroll
            for (int j = 0; j < BN / 32; j++) {
                int r = sr + j * 32;
                int n = col0 + r; if (n >= N) n = N - 1;
                cp16(stB + (r * 32) * 4 + swoff * 4,
                     Bp + (long long)n * 512);
            }
        }
        CP_COMMIT();
    };

    float acc[2][NT][4];
    #pragma unroll
    for (int mt = 0; mt < 2; mt++)
        #pragma unroll
        for (int nt = 0; nt < NT; nt++)
            #pragma unroll
            for (int q = 0; q < 4; q++) acc[mt][nt][q] = 0.f;

    issue(0);
    issue(1);

    for (int cc = 0; cc < ncc; cc++) {
        CP_WAIT1();
        __syncthreads();
        issue(cc + 2);

        const uint32_t* uA = reinterpret_cast<const uint32_t*>(sm + (cc % 3) * STAGE);
        const uint32_t* uB = uA + AW;

        #pragma unroll
        for (int ks = 0; ks < 4; ks++) {
            const int k4 = ks * 2;
            const uint32_t x0 = (uint32_t)(((k4 ^ gid) << 2) + tig);
            const uint32_t x1 = (uint32_t)((((k4 + 1) ^ gid) << 2) + tig);
            uint32_t aF[2][4];
            #pragma unroll
            for (int mt = 0; mt < 2; mt++) {
                const int ml = mbase + mt * 16 + gid;
                const int mh = ml + 8;
                aF[mt][0] = uA[ml * 32 + x0];
                aF[mt][1] = uA[mh * 32 + x0];
                aF[mt][2] = uA[ml * 32 + x1];
                aF[mt][3] = uA[mh * 32 + x1];
            }
            #pragma unroll
            for (int nt = 0; nt < NT; nt++) {
                const int n = nbase + nt * 8 + gid;
                uint32_t bF[2];
                bF[0] = uB[n * 32 + x0];
                bF[1] = uB[n * 32 + x1];
                MMA_TF32(acc[0][nt], aF[0], bF);
                MMA_TF32(acc[1][nt], aF[1], bF);
            }
        }
    }

    float* Cz = C + (long long)z * sC;
    const float* bz = bias ? (bias + (long long)z * sBias) : nullptr;
    const bool even = ((ldc & 1) == 0);
    #pragma unroll
    for (int mt = 0; mt < 2; mt++) {
        const int rlo = row0 + mbase + mt * 16 + gid;
        const int rhi = rlo + 8;
        #pragma unroll
        for (int nt = 0; nt < NT; nt++) {
            const int n0 = col0 + nbase + nt * 8 + 2 * tig;
            if (n0 >= N) continue;
            float b0v = bz ? bz[n0] : 0.f;
            float b1v = (bz && n0 + 1 < N) ? bz[n0 + 1] : 0.f;
            float c0 = acc[mt][nt][0] + b0v;
            float c1 = acc[mt][nt][1] + b1v;
            float c2 = acc[mt][nt][2] + b0v;
            float c3 = acc[mt][nt][3] + b1v;
            if (even && (n0 + 1 < N)) {
                *reinterpret_cast<float2*>(Cz + (long long)rlo * ldc + n0) = make_float2(c0, c1);
                *reinterpret_cast<float2*>(Cz + (long long)rhi * ldc + n0) = make_float2(c2, c3);
            } else {
                Cz[(long long)rlo * ldc + n0] = c0;
                Cz[(long long)rhi * ldc + n0] = c2;
                if (n0 + 1 < N) {
                    Cz[(long long)rlo * ldc + n0 + 1] = c1;
                    Cz[(long long)rhi * ldc + n0 + 1] = c3;
                }
            }
        }
    }
}

// ---------------------------------------------------------------------------
// Merged f16 logits GEMM, all 4 calls (z = call index 0..3), ldmatrix feeds.
// __launch_bounds__(256,2): 2 CTAs/SM (regs<=128, smem 2x96KB w/ carveout)
// ---------------------------------------------------------------------------
__global__ __launch_bounds__(256, 2)
void gemm_f16s(const __half* __restrict__ Ah, const __half* __restrict__ BhAll,
               const float* __restrict__ biasAll, const float* __restrict__ hh2,
               const float* __restrict__ wAll,
               __half* __restrict__ Mout, float* __restrict__ scorep)
{
    constexpr int AW    = 128 * 32;      // u32 per A stage
    constexpr int STAGE = AW + AW;

    extern __shared__ uint32_t smu[];
    __shared__ float sred[128];

    const int tid   = threadIdx.x;
    const int warp  = tid >> 5;
    const int lane  = tid & 31;
    const int gid   = lane >> 2;
    const int tig   = lane & 3;
    const int mbase = (warp & 3) * 32;
    const int nbase = (warp >> 2) * 64;

    const int row0 = blockIdx.y * 128;
    const int col0 = blockIdx.x * 128;
    const int z    = blockIdx.z;

    const __half* Bz = BhAll + (size_t)z * A_ * R_;

    const int sr  = tid >> 3;
    const int sc8 = tid & 7;
    const uint32_t smbase = smem_u32(smu);
    const uint32_t swoff  = (uint32_t)((sc8 ^ (sr & 7)) << 2);

    if (tid < 128) sred[tid] = 0.f;

    // ldmatrix lane geometry
    const int l15  = lane & 15;
    const int gAhi = lane >> 4;                       // A: k-half select
    const int rB   = (lane & 7) + ((lane & 16) >> 1); // B: row within 16
    const int gBlo = (lane >> 3) & 1;                 // B: k-half select

    auto issue = [&](int cc) {
        if (cc < 8) {
            const int kb = cc * 64;                  // halves
            const uint32_t stA = smbase + (uint32_t)(cc % 3) * (STAGE * 4);
            const uint32_t stB = stA + AW * 4;
            #pragma unroll
            for (int j = 0; j < 4; j++) {
                int r = sr + j * 32;
                cp16(stA + (r * 32) * 4 + swoff * 4,
                     Ah + (long long)(row0 + r) * 512 + kb + sc8 * 8);
                int n = col0 + r; if (n >= A_) n = A_ - 1;
                cp16(stB + (r * 32) * 4 + swoff * 4,
                     Bz + (long long)n * 512 + kb + sc8 * 8);
            }
        }
        CP_COMMIT();
    };

    float acc[2][8][4];
    #pragma unroll
    for (int mt = 0; mt < 2; mt++)
        #pragma unroll
        for (int nt = 0; nt < 8; nt++)
            #pragma unroll
            for (int q = 0; q < 4; q++) acc[mt][nt][q] = 0.f;

    issue(0);
    issue(1);

    for (int cc = 0; cc < 8; cc++) {
        CP_WAIT1();
        __syncthreads();
        issue(cc + 2);

        const uint32_t stA = smbase + (uint32_t)(cc % 3) * (STAGE * 4);
        const uint32_t stB = stA + AW * 4;

        #pragma unroll
        for (int ks = 0; ks < 4; ks++) {
            uint32_t aF[2][4];
            #pragma unroll
            for (int mt = 0; mt < 2; mt++) {
                const int rA = mbase + mt * 16 + l15;
                const uint32_t g = (uint32_t)((2 * ks + gAhi) ^ (rA & 7));
                LDSM_X4(aF[mt][0], aF[mt][1], aF[mt][2], aF[mt][3],
                        stA + (uint32_t)rA * 128 + (g << 4));
            }
            #pragma unroll
            for (int p = 0; p < 4; p++) {
                const int rBB = nbase + p * 16 + rB;
                const uint32_t g = (uint32_t)((2 * ks + gBlo) ^ (rBB & 7));
                uint32_t b0, b1, b2, b3;
                LDSM_X4(b0, b1, b2, b3, stB + (uint32_t)rBB * 128 + (g << 4));
                MMA_F16(acc[0][2 * p],     aF[0], b0, b1);
                MMA_F16(acc[1][2 * p],     aF[1], b0, b1);
                MMA_F16(acc[0][2 * p + 1], aF[0], b2, b3);
                MMA_F16(acc[1][2 * p + 1], aF[1], b2, b3);
            }
        }
    }

    const float* bz = biasAll + (size_t)z * A_;

    if (z & 1) {
        // write half logits into gMh at column offset z*A_
        __half* Cz = Mout;
        #pragma unroll
        for (int mt = 0; mt < 2; mt++) {
            const int rlo = row0 + mbase + mt * 16 + gid;
            const int rhi = rlo + 8;
            #pragma unroll
            for (int nt = 0; nt < 8; nt++) {
                const int n0 = col0 + nbase + nt * 8 + 2 * tig;
                if (n0 >= A_) continue;
                float b0v = bz[n0], b1v = bz[n0 + 1];
                *reinterpret_cast<__half2*>(Cz + (long long)rlo * KC_ + z * A_ + n0) =
                    __floats2half2_rn(acc[mt][nt][0] + b0v, acc[mt][nt][1] + b1v);
                *reinterpret_cast<__half2*>(Cz + (long long)rhi * KC_ + z * A_ + n0) =
                    __floats2half2_rn(acc[mt][nt][2] + b0v, acc[mt][nt][3] + b1v);
            }
        }
    } else {
        const int zl = z >> 1;
        const float* hz = hh2 + (size_t)zl * BA_;
        const float* wz = wAll + (size_t)z * A_;
        __syncthreads();   // sred zeroed
        #pragma unroll
        for (int mt = 0; mt < 2; mt++) {
            const int rlo = row0 + mbase + mt * 16 + gid;
            const int rhi = rlo + 8;
            const float hl = hz[rlo], hb = hz[rhi];
            float plo = 0.f, phi = 0.f;
            #pragma unroll
            for (int nt = 0; nt < 8; nt++) {
                const int n0 = col0 + nbase + nt * 8 + 2 * tig;
                if (n0 >= A_) continue;
                const float b0v = bz[n0], b1v = bz[n0 + 1];
                const float w0v = wz[n0], w1v = wz[n0 + 1];
                float2 tl = __half22float2(htanh2(__floats2half2_rn(
                    acc[mt][nt][0] + b0v + hl, acc[mt][nt][1] + b1v + hl)));
                float2 th = __half22float2(htanh2(__floats2half2_rn(
                    acc[mt][nt][2] + b0v + hb, acc[mt][nt][3] + b1v + hb)));
                plo = fmaf(tl.x, w0v, fmaf(tl.y, w1v, plo));
                phi = fmaf(th.x, w0v, fmaf(th.y, w1v, phi));
            }
            plo += __shfl_xor_sync(0xFFFFFFFFu, plo, 1);
            plo += __shfl_xor_sync(0xFFFFFFFFu, plo, 2);
            phi += __shfl_xor_sync(0xFFFFFFFFu, phi, 1);
            phi += __shfl_xor_sync(0xFFFFFFFFu, phi, 2);
            if (tig == 0) {
                atomicAdd(&sred[mbase + mt * 16 + gid], plo);
                atomicAdd(&sred[mbase + mt * 16 + gid + 8], phi);
            }
        }
        __syncthreads();
        if (tid < 128)
            scorep[(size_t)(zl * 2 + blockIdx.x) * BA_ + row0 + tid] = sred[tid];
    }
}

// ---------------------------------------------------------------------------
// fp32 -> half conversion
// ---------------------------------------------------------------------------
__global__ __launch_bounds__(256)
void conv_half(const float4* __restrict__ in, __half2* __restrict__ outp)
{
    const int i = blockIdx.x * 256 + threadIdx.x;
    float4 v = in[i];
    outp[2 * i]     = __floats2half2_rn(v.x, v.y);
    outp[2 * i + 1] = __floats2half2_rn(v.z, v.w);
}

// ---------------------------------------------------------------------------
// Score from 4 K-split hh partials + per-a bias (calls 1,3)
// ---------------------------------------------------------------------------
__global__ __launch_bounds__(256)
void score4_kernel(const __half* __restrict__ Mh, const float* __restrict__ hhp,
                   const float* __restrict__ hbias,
                   const float* __restrict__ w, const float* __restrict__ d2db,
                   float* __restrict__ score, int col_off)
{
    const int id   = blockIdx.x * 8 + (threadIdx.x >> 5);
    const int lane = threadIdx.x & 31;
    const float h  = hhp[id] + hhp[BA_ + id] + hhp[2 * BA_ + id] + hhp[3 * BA_ + id]
                   + hbias[id % A_];
    const __half2* row = reinterpret_cast<const __half2*>(
        Mh + (size_t)id * KC_ + col_off);
    const float2* w2 = reinterpret_cast<const float2*>(w);
    const __half2 h2 = __float2half2_rn(h);
    float s = 0.f;
    for (int k = lane; k < A_ / 2; k += 32) {
        float2 tf = __half22float2(htanh2(__hadd2(row[k], h2)));
        float2 ww = w2[k];
        s = fmaf(tf.x, ww.x, s);
        s = fmaf(tf.y, ww.y, s);
    }
    #pragma unroll
    for (int o = 16; o > 0; o >>= 1)
        s += __shfl_xor_sync(0xFFFFFFFFu, s, o);
    if (lane == 0) score[id] = s + d2db[0];
}

// ---------------------------------------------------------------------------
// Softmax helper from explicit logit values
// ---------------------------------------------------------------------------
__device__ __forceinline__ void softmax_vals(float l0, float l1, float* sw,
                                             float* red, int tid)
{
    const int t2 = tid + 128;
    red[tid] = fmaxf(l0, l1); __syncthreads();
    for (int s = 64; s > 0; s >>= 1) {
        if (tid < s) red[tid] = fmaxf(red[tid], red[tid + s]);
        __syncthreads();
    }
    const float mx = red[0]; __syncthreads();
    float e0 = mexp(l0 - mx);
    float e1 = (t2 < A_) ? mexp(l1 - mx) : 0.f;
    red[tid] = e0 + e1; __syncthreads();
    for (int s = 64; s > 0; s >>= 1) {
        if (tid < s) red[tid] += red[tid + s];
        __syncthreads();
    }
    const float inv = 1.f / red[0];
    sw[tid] = e0 * inv;
    if (t2 < A_) sw[t2] = e1 * inv;
    __syncthreads();
}

// ---------------------------------------------------------------------------
// Dual weighted sum from fused-score partials (calls 0,2)
// ---------------------------------------------------------------------------
__global__ __launch_bounds__(128)
void wsum2_sm(const __half2* __restrict__ atth, const float* __restrict__ sp,
              const float* __restrict__ d2db, float* __restrict__ outp)
{
    const int b   = blockIdx.y;
    const int tid = threadIdx.x;
    __shared__ float w0[A_], w1[A_];
    __shared__ float red[128];

    const int i0 = b * A_ + tid;
    const int i1 = i0 + 128;
    const bool v1 = (tid + 128) < A_;
    {
        float db = d2db[0];
        float l0 = sp[i0] + sp[BA_ + i0] + db;
        float l1 = v1 ? (sp[i1] + sp[BA_ + i1] + db) : -INFINITY;
        softmax_vals(l0, l1, w0, red, tid);
    }
    {
        float db = d2db[2];
        float l0 = sp[2 * BA_ + i0] + sp[3 * BA_ + i0] + db;
        float l1 = v1 ? (sp[2 * BA_ + i1] + sp[3 * BA_ + i1] + db) : -INFINITY;
        softmax_vals(l0, l1, w1, red, tid);
    }

    const __half2* ab = atth + (((size_t)b * A_ * R_) >> 1)
                       + (blockIdx.x * 256 >> 1) + tid;
    float ax = 0.f, ay = 0.f, bx = 0.f, by = 0.f;
    #pragma unroll 14
    for (int a = 0; a < A_; a++) {
        float2 f = __half22float2(ab[a * (R_ / 2)]);
        ax = fmaf(f.x, w0[a], ax); ay = fmaf(f.y, w0[a], ay);
        bx = fmaf(f.x, w1[a], bx); by = fmaf(f.y, w1[a], by);
    }
    const int r = blockIdx.x * 256 + tid * 2;
    *reinterpret_cast<float2*>(outp + b * R_ + r)           = make_float2(ax, ay);
    *reinterpret_cast<float2*>(outp + B_ * R_ + b * R_ + r) = make_float2(bx, by);
}

// Single weighted sum + softmax from score buffer (+ addv)
__global__ __launch_bounds__(128)
void wsum_sm(const __half2* __restrict__ atth, const float* __restrict__ score,
             const float* __restrict__ addv, float* __restrict__ outp)
{
    const int b   = blockIdx.y;
    const int tid = threadIdx.x;
    __shared__ float w0[A_];
    __shared__ float red[128];

    const float* sc = score + b * A_;
    float l0 = sc[tid];
    float l1 = (tid + 128 < A_) ? sc[tid + 128] : -INFINITY;
    softmax_vals(l0, l1, w0, red, tid);

    const __half2* ab = atth + (((size_t)b * A_ * R_) >> 1)
                       + (blockIdx.x * 256 >> 1) + tid;
    float ax = 0.f, ay = 0.f;
    #pragma unroll 14
    for (int a = 0; a < A_; a++) {
        float2 f = __half22float2(ab[a * (R_ / 2)]);
        ax = fmaf(f.x, w0[a], ax);
        ay = fmaf(f.y, w0[a], ay);
    }
    const int r = blockIdx.x * 256 + tid * 2;
    float2 av = *reinterpret_cast<const float2*>(addv + b * R_ + r);
    *reinterpret_cast<float2*>(outp + b * R_ + r) = make_float2(ax + av.x, ay + av.y);
}

// ---------------------------------------------------------------------------
// Gates + cell update + mean over P
// ---------------------------------------------------------------------------
__global__ __launch_bounds__(256)
void gate_kernel(const float* __restrict__ sums,
                 const float* __restrict__ bi, const float* __restrict__ bh,
                 const float* __restrict__ ba,
                 const float* __restrict__ prev_c,
                 float* __restrict__ next_c, float* __restrict__ next_h)
{
    const int idx = blockIdx.x * 256 + threadIdx.x;
    const int b = idx >> 9, r = idx & (R_ - 1);
    const float pc = prev_c[idx];
    float ca = 0.f, ha = 0.f;
    #pragma unroll
    for (int p = 0; p < P_; p++) {
        const long long base = ((long long)p * B_ + b) * G4_;
        const int bb = p * G4_;
        float si = sums[base + r]        + bi[bb + r]        + bh[bb + r]        + ba[bb + r];
        float sf = sums[base + R_ + r]   + bi[bb + R_ + r]   + bh[bb + R_ + r]   + ba[bb + R_ + r];
        float so = sums[base + 2*R_ + r] + bi[bb + 2*R_ + r] + bh[bb + 2*R_ + r] + ba[bb + 2*R_ + r];
        float st = sums[base + 3*R_ + r] + bi[bb + 3*R_ + r] + bh[bb + 3*R_ + r] + ba[bb + 3*R_ + r];
        float ig = msig(si);
        float fg = msig(sf);
        float og = msig(so);
        float it = mtanh(st);
        float nc = fg * pc + ig * it;
        ca += nc;
        ha += og * mtanh(nc);
    }
    next_c[idx] = ca * (1.f / 3.f);
    next_h[idx] = ha * (1.f / 3.f);
}

__global__ __launch_bounds__(256)
void add_kernel(float* __restrict__ o, const float* __restrict__ a,
                const float* __restrict__ b)
{
    int i = blockIdx.x * 256 + threadIdx.x;
    o[i] = a[i] + b[i];
}

// ---------------------------------------------------------------------------
// In-place log-softmax over V per row
// ---------------------------------------------------------------------------
__global__ __launch_bounds__(256)
void logsoftmax_kernel(float* __restrict__ x)
{
    const int b = blockIdx.x, tid = threadIdx.x;
    __shared__ float red[256];
    float* row = x + (long long)b * V_;

    float mx = -INFINITY;
    for (int i = tid; i < V_; i += 256) mx = fmaxf(mx, row[i]);
    red[tid] = mx; __syncthreads();
    for (int s = 128; s > 0; s >>= 1) {
        if (tid < s) red[tid] = fmaxf(red[tid], red[tid + s]);
        __syncthreads();
    }
    mx = red[0]; __syncthreads();

    float sum = 0.f;
    for (int i = tid; i < V_; i += 256) sum += mexp(row[i] - mx);
    red[tid] = sum; __syncthreads();
    for (int s = 128; s > 0; s >>= 1) {
        if (tid < s) red[tid] += red[tid + s];
        __syncthreads();
    }
    const float lz = logf(red[0]) + mx;
    for (int i = tid; i < V_; i += 256) row[i] = row[i] - lz;
}

// ---------------------------------------------------------------------------
// Host launch
// ---------------------------------------------------------------------------
extern "C" void kernel_launch(void* const* d_in, const int* in_sizes, int n_in,
                              void* d_out, int out_size)
{
    (void)in_sizes; (void)n_in; (void)out_size;
    const float* x      = (const float*)d_in[0];
    const float* att    = (const float*)d_in[1];
    const float* inputs = (const float*)d_in[2];
    const float* i2h_w  = (const float*)d_in[3];
    const float* i2h_b  = (const float*)d_in[4];
    const float* h2h_w  = (const float*)d_in[5];
    const float* h2h_b  = (const float*)d_in[6];
    const float* a2h_w  = (const float*)d_in[7];
    const float* a2h_b  = (const float*)d_in[8];
    const float* a2a_w  = (const float*)d_in[9];
    const float* a2a_b  = (const float*)d_in[10];
    const float* h2a_w  = (const float*)d_in[11];
    const float* h2a_b  = (const float*)d_in[12];
    const float* d2d_w  = (const float*)d_in[13];
    const float* d2d_b  = (const float*)d_in[14];
    const float* proj_w = (const float*)d_in[15];
    const float* proj_b = (const float*)d_in[16];
    float* out = (float*)d_out;

    __half *pMh, *patth, *pa2awh;
    float *phh2, *phhp, *pscore, *pscorep, *patt0, *psums, *pxt, *pnh;
    cudaGetSymbolAddress((void**)&pMh,     gMh);
    cudaGetSymbolAddress((void**)&patth,   g_atth);
    cudaGetSymbolAddress((void**)&pa2awh,  g_a2awh);
    cudaGetSymbolAddress((void**)&phh2,    g_hh2);
    cudaGetSymbolAddress((void**)&phhp,    g_hhp);
    cudaGetSymbolAddress((void**)&pscore,  g_score);
    cudaGetSymbolAddress((void**)&pscorep, g_scorep);
    cudaGetSymbolAddress((void**)&patt0,   g_att0);
    cudaGetSymbolAddress((void**)&psums,   g_sums);
    cudaGetSymbolAddress((void**)&pxt,     g_xt);
    cudaGetSymbolAddress((void**)&pnh,     g_nh);

    static bool attr_done = false;
    const int smem128 = 3 * (128 + 128) * 32 * 4;  // 98304
    const int smem64  = 3 * (128 + 64)  * 32 * 4;  // 73728
    if (!attr_done) {
        cudaFuncSetAttribute(gemm_mma<128>, cudaFuncAttributeMaxDynamicSharedMemorySize, smem128);
        cudaFuncSetAttribute(gemm_mma<64>,  cudaFuncAttributeMaxDynamicSharedMemorySize, smem64);
        cudaFuncSetAttribute(gemm_f16s,     cudaFuncAttributeMaxDynamicSharedMemorySize, smem128);
        // opt into the full shared-memory carveout so TWO 96KB CTAs co-reside
        cudaFuncSetAttribute(gemm_f16s,
                             cudaFuncAttributePreferredSharedMemoryCarveout, 100);
        cudaFuncSetAttribute(gemm_mma<64>,
                             cudaFuncAttributePreferredSharedMemoryCarveout, 100);
        cudaFuncSetAttribute(gemm_mma<128>,
                             cudaFuncAttributePreferredSharedMemoryCarveout, 100);
        attr_done = true;
    }

    dim3 blk(256);
    const size_t wst = (size_t)G4_ * R_;
    const __half2* atth2 = reinterpret_cast<const __half2*>(patth);

    // 0) conversions to half
    conv_half<<<(B_ * A_ * R_) / 4 / 256, blk>>>(
        reinterpret_cast<const float4*>(att), reinterpret_cast<__half2*>(patth));
    conv_half<<<(KC_ * R_) / 4 / 256, blk>>>(
        reinterpret_cast<const float4*>(a2a_w), reinterpret_cast<__half2*>(pa2awh));

    // 1) hh2 for call0 of both layers (z = layer)
    {
        const float* ph = inputs + (size_t)B_ * R_;
        gemm_mma<64><<<dim3(4, 2, 2), blk, smem64>>>(
            ph, ph, ph, h2a_w, h2a_w, h2a_w, phh2, h2a_b,
            A_, R_, A_,
            (long long)2 * B_ * R_, (long long)2 * A_ * R_,
            (long long)B_ * A_, (long long)2 * A_);
    }

    // 2) merged f16 logits GEMM: fused score (calls 0,2) + logits out (1,3)
    gemm_f16s<<<dim3(2, BA_ / 128, 4), blk, smem128>>>(
        patth, pa2awh, a2a_b, phh2, d2d_w, pMh, pscorep);

    // 3) att_res0 for both layers from fused-score partials
    wsum2_sm<<<dim3(R_ / 256, B_), dim3(128)>>>(atth2, pscorep, d2d_b, patt0);

    for (int i = 0; i < L_; i++) {
        const float* prev_c = inputs + (size_t)(2 * i) * B_ * R_;
        const float* prev_h = inputs + (size_t)(2 * i + 1) * B_ * R_;
        const int c1 = 2 * i + 1;

        const float* xt = x;
        if (i == 1) {
            add_kernel<<<(B_ * R_) / 256, blk>>>(pxt, x, out + (size_t)1 * B_ * R_);
            xt = pxt;
        }

        // fused gate GEMM: K=1536, A segs [xt, prev_h, att0_i]
        gemm_mma<64><<<dim3(32, 2, P_), blk, smem64>>>(
            xt, prev_h, patt0 + (size_t)i * B_ * R_,
            i2h_w + (size_t)i * P_ * wst,
            h2h_w + (size_t)i * P_ * wst,
            a2h_w + (size_t)i * P_ * wst,
            psums, nullptr,
            G4_, 3 * R_, G4_,
            0, (long long)wst, (long long)B_ * G4_, 0);

        gate_kernel<<<(B_ * R_) / 256, blk>>>(
            psums,
            i2h_b + (size_t)i * P_ * G4_,
            h2h_b + (size_t)i * P_ * G4_,
            a2h_b + (size_t)i * P_ * G4_,
            prev_c,
            out + (size_t)(2 * i) * B_ * R_, pnh);

        // call1 hh: K-split x4 into partials (z = k-slice of 128)
        {
            const float* bw = h2a_w + (size_t)c1 * A_ * R_;
            gemm_mma<64><<<dim3(4, 2, 4), blk, smem64>>>(
                pnh, pnh, pnh, bw, bw, bw, phhp, nullptr,
                A_, 128, A_,
                128, 128, (long long)BA_, 0);
        }
        score4_kernel<<<BA_ / 8, blk>>>(pMh, phhp, h2a_b + (size_t)c1 * A_,
                                        d2d_w + (size_t)c1 * A_, d2d_b + c1,
                                        pscore, c1 * A_);
        wsum_sm<<<dim3(R_ / 256, B_), dim3(128)>>>(
            atth2, pscore, pnh, out + (size_t)(2 * i + 1) * B_ * R_);
    }

    // projection + log-softmax
    gemm_mma<64><<<dim3((V_ + 63) / 64, 2, 1), blk, smem64>>>(
        out + (size_t)3 * B_ * R_, out, out,
        proj_w, proj_w, proj_w,
        out + (size_t)4 * B_ * R_, proj_b,
        V_, R_, V_, 0, 0, 0, 0);
    logsoftmax_kernel<<<B_, blk>>>(out + (size_t)4 * B_ * R_);
}

// round 11
// speedup vs baseline: 1.0764x; 1.0764x over previous
#include <cuda_runtime.h>
#include <cuda_fp16.h>
#include <math.h>
#include <stdint.h>

// Problem constants
#define L_   2
#define P_   3
#define R_   512
#define A_   196
#define V_   9487
#define B_   256
#define BA_  (B_*A_)        // 50176
#define KC_  (2*L_*A_)      // 784
#define G4_  (4*R_)         // 2048

// ---------------------------------------------------------------------------
// Static device scratch (allocation-free)
// ---------------------------------------------------------------------------
__device__ __half gMh    [(size_t)BA_ * KC_];     // logits half (calls 1,3 cols)
__device__ __half g_atth [(size_t)B_ * A_ * R_];  // att half
__device__ __half g_a2awh[(size_t)KC_ * R_];
__device__ __half g_i2hwh[(size_t)L_ * P_ * G4_ * R_];
__device__ __half g_h2hwh[(size_t)L_ * P_ * G4_ * R_];
__device__ __half g_a2hwh[(size_t)L_ * P_ * G4_ * R_];
__device__ __half g_h2awh[(size_t)L_ * 2 * A_ * R_];
__device__ __half g_projwh[(size_t)V_ * R_];
__device__ __half g_inh  [2 * B_ * R_];           // prev_h of both layers, half
__device__ __half g_xth  [B_ * R_];
__device__ __half g_att0h[2 * B_ * R_];
__device__ __half g_nhh  [B_ * R_];
__device__ __half g_thh  [B_ * R_];               // top_h layer1, half
__device__ float g_hh2  [2 * B_ * A_];
__device__ float g_hhp  [4 * B_ * A_];
__device__ float g_score[BA_];
__device__ float g_scorep[4 * BA_];
__device__ float g_sums [P_ * B_ * G4_];
__device__ float g_nh   [B_ * R_];

// ---------------------------------------------------------------------------
// MUFU-based activations
// ---------------------------------------------------------------------------
__device__ __forceinline__ float mexp(float x) {
    float r;
    asm("ex2.approx.f32 %0, %1;" : "=f"(r) : "f"(x * 1.4426950408889634f));
    return r;
}
__device__ __forceinline__ float msig(float x) {
    float t = fminf(-1.4426950408889634f * x, 126.0f);
    float u;
    asm("ex2.approx.f32 %0, %1;" : "=f"(u) : "f"(t));
    float d = 1.0f + u;
    float r;
    asm("rcp.approx.f32 %0, %1;" : "=f"(r) : "f"(d));
    r = r * fmaf(-d, r, 2.0f);
    return r;
}
__device__ __forceinline__ float mtanh(float x) {
    return fmaf(2.0f, msig(2.0f * x), -1.0f);
}
__device__ __forceinline__ __half2 htanh2(__half2 v) {
    uint32_t vi = *reinterpret_cast<uint32_t*>(&v);
    uint32_t to;
    asm("tanh.approx.f16x2 %0, %1;" : "=r"(to) : "r"(vi));
    return *reinterpret_cast<__half2*>(&to);
}

// ---------------------------------------------------------------------------
// mma / cp.async / ldmatrix helpers
// ---------------------------------------------------------------------------
#define MMA_F16(c, a, b0, b1) \
    asm volatile("mma.sync.aligned.m16n8k16.row.col.f32.f16.f16.f32 " \
        "{%0,%1,%2,%3}, {%4,%5,%6,%7}, {%8,%9}, {%0,%1,%2,%3};" \
        : "+f"((c)[0]), "+f"((c)[1]), "+f"((c)[2]), "+f"((c)[3]) \
        : "r"((a)[0]), "r"((a)[1]), "r"((a)[2]), "r"((a)[3]), \
          "r"(b0), "r"(b1))

#define LDSM_X4(r0, r1, r2, r3, addr) \
    asm volatile("ldmatrix.sync.aligned.m8n8.x4.shared.b16 {%0,%1,%2,%3}, [%4];" \
        : "=r"(r0), "=r"(r1), "=r"(r2), "=r"(r3) : "r"(addr))

__device__ __forceinline__ uint32_t smem_u32(const void* p) {
    uint32_t a;
    asm("{ .reg .u64 t; cvta.to.shared.u64 t, %1; cvt.u32.u64 %0, t; }" : "=r"(a) : "l"(p));
    return a;
}
__device__ __forceinline__ void cp16(uint32_t dst, const void* src) {
    asm volatile("cp.async.cg.shared.global [%0], [%1], 16;" :: "r"(dst), "l"(src));
}
#define CP_COMMIT() asm volatile("cp.async.commit_group;" ::: "memory")
#define CP_WAIT1()  asm volatile("cp.async.wait_group 1;" ::: "memory")

// ---------------------------------------------------------------------------
// Generic f16 NT GEMM, fp32 out: C[m,n] = sum_k A[m,k]*B[n,k] (+bias[n])
// 128 x BN tiles, BK=64 halves, 3-stage cp.async + ldmatrix.
// A and B segmented into up to 3 K-sources of 512 halves (rows stride 512).
// Strides sA/sB in halves, sC/sBias in floats. M multiple of 128.
// ---------------------------------------------------------------------------
template<int BN>
__global__ __launch_bounds__(256, 2)
void gemm_f16h(const __half* __restrict__ A0, const __half* __restrict__ A1,
               const __half* __restrict__ A2,
               const __half* __restrict__ B0, const __half* __restrict__ B1,
               const __half* __restrict__ B2,
               float* __restrict__ C, const float* __restrict__ bias,
               int N, int Ktot, int ldc,
               long long sA, long long sB, long long sC, long long sBias)
{
    constexpr int NT    = BN / 16;
    constexpr int AWu   = 128 * 32;        // u32 per A stage (128 rows x 128B)
    constexpr int BWu   = BN * 32;
    constexpr int STAGE = AWu + BWu;

    extern __shared__ uint32_t smu[];

    const int tid   = threadIdx.x;
    const int warp  = tid >> 5;
    const int lane  = tid & 31;
    const int gid   = lane >> 2;
    const int tig   = lane & 3;
    const int mbase = (warp & 3) * 32;
    const int nbase = (warp >> 2) * (BN / 2);

    const int row0 = blockIdx.y * 128;
    const int col0 = blockIdx.x * BN;
    const int z    = blockIdx.z;

    const int sr  = tid >> 3;
    const int sc8 = tid & 7;
    const uint32_t smbase = smem_u32(smu);
    const uint32_t swoff  = (uint32_t)((sc8 ^ (sr & 7)) << 2);

    // ldmatrix lane geometry
    const int l15  = lane & 15;
    const int gAhi = lane >> 4;
    const int rB   = (lane & 7) + ((lane & 16) >> 1);
    const int gBlo = (lane >> 3) & 1;

    const int ncc = Ktot >> 6;             // 64-half chunks

    auto issue = [&](int cc) {
        if (cc < ncc) {
            const int kb  = cc << 6;
            const int seg = kb >> 9;
            const int kbl = kb & 511;
            const __half* Ap = ((seg == 0) ? A0 : (seg == 1) ? A1 : A2)
                               + (long long)z * sA + kbl + sc8 * 8;
            const __half* Bp = ((seg == 0) ? B0 : (seg == 1) ? B1 : B2)
                               + (long long)z * sB + kbl + sc8 * 8;
            const uint32_t stA = smbase + (uint32_t)(cc % 3) * (STAGE * 4);
            const uint32_t stB = stA + AWu * 4;
            #pragma unroll
            for (int j = 0; j < 4; j++) {
                int r = sr + j * 32;
                cp16(stA + (r * 32) * 4 + swoff * 4,
                     Ap + (long long)(row0 + r) * 512);
            }
            #pragma unroll
            for (int j = 0; j < BN / 32; j++) {
                int r = sr + j * 32;
                int n = col0 + r; if (n >= N) n = N - 1;
                cp16(stB + (r * 32) * 4 + swoff * 4,
                     Bp + (long long)n * 512);
            }
        }
        CP_COMMIT();
    };

    float acc[2][NT][4];
    #pragma unroll
    for (int mt = 0; mt < 2; mt++)
        #pragma unroll
        for (int nt = 0; nt < NT; nt++)
            #pragma unroll
            for (int q = 0; q < 4; q++) acc[mt][nt][q] = 0.f;

    issue(0);
    issue(1);

    for (int cc = 0; cc < ncc; cc++) {
        CP_WAIT1();
        __syncthreads();
        issue(cc + 2);

        const uint32_t stA = smbase + (uint32_t)(cc % 3) * (STAGE * 4);
        const uint32_t stB = stA + AWu * 4;

        #pragma unroll
        for (int ks = 0; ks < 4; ks++) {
            uint32_t aF[2][4];
            #pragma unroll
            for (int mt = 0; mt < 2; mt++) {
                const int rA = mbase + mt * 16 + l15;
                const uint32_t g = (uint32_t)((2 * ks + gAhi) ^ (rA & 7));
                LDSM_X4(aF[mt][0], aF[mt][1], aF[mt][2], aF[mt][3],
                        stA + (uint32_t)rA * 128 + (g << 4));
            }
            #pragma unroll
            for (int p = 0; p < BN / 32; p++) {
                const int rBB = nbase + p * 16 + rB;
                const uint32_t g = (uint32_t)((2 * ks + gBlo) ^ (rBB & 7));
                uint32_t b0, b1, b2, b3;
                LDSM_X4(b0, b1, b2, b3, stB + (uint32_t)rBB * 128 + (g << 4));
                MMA_F16(acc[0][2 * p],     aF[0], b0, b1);
                MMA_F16(acc[1][2 * p],     aF[1], b0, b1);
                MMA_F16(acc[0][2 * p + 1], aF[0], b2, b3);
                MMA_F16(acc[1][2 * p + 1], aF[1], b2, b3);
            }
        }
    }

    float* Cz = C + (long long)z * sC;
    const float* bz = bias ? (bias + (long long)z * sBias) : nullptr;
    const bool even = ((ldc & 1) == 0);
    #pragma unroll
    for (int mt = 0; mt < 2; mt++) {
        const int rlo = row0 + mbase + mt * 16 + gid;
        const int rhi = rlo + 8;
        #pragma unroll
        for (int nt = 0; nt < NT; nt++) {
            const int n0 = col0 + nbase + nt * 8 + 2 * tig;
            if (n0 >= N) continue;
            float b0v = bz ? bz[n0] : 0.f;
            float b1v = (bz && n0 + 1 < N) ? bz[n0 + 1] : 0.f;
            float c0 = acc[mt][nt][0] + b0v;
            float c1 = acc[mt][nt][1] + b1v;
            float c2 = acc[mt][nt][2] + b0v;
            float c3 = acc[mt][nt][3] + b1v;
            if (even && (n0 + 1 < N)) {
                *reinterpret_cast<float2*>(Cz + (long long)rlo * ldc + n0) = make_float2(c0, c1);
                *reinterpret_cast<float2*>(Cz + (long long)rhi * ldc + n0) = make_float2(c2, c3);
            } else {
                Cz[(long long)rlo * ldc + n0] = c0;
                Cz[(long long)rhi * ldc + n0] = c2;
                if (n0 + 1 < N) {
                    Cz[(long long)rlo * ldc + n0 + 1] = c1;
                    Cz[(long long)rhi * ldc + n0 + 1] = c3;
                }
            }
        }
    }
}

// ---------------------------------------------------------------------------
// Merged f16 logits GEMM (unchanged from R9): fused score (z even) / logits out
// ---------------------------------------------------------------------------
__global__ __launch_bounds__(256, 2)
void gemm_f16s(const __half* __restrict__ Ah, const __half* __restrict__ BhAll,
               const float* __restrict__ biasAll, const float* __restrict__ hh2,
               const float* __restrict__ wAll,
               __half* __restrict__ Mout, float* __restrict__ scorep)
{
    constexpr int AW    = 128 * 32;
    constexpr int STAGE = AW + AW;

    extern __shared__ uint32_t smu[];
    __shared__ float sred[128];

    const int tid   = threadIdx.x;
    const int warp  = tid >> 5;
    const int lane  = tid & 31;
    const int gid   = lane >> 2;
    const int tig   = lane & 3;
    const int mbase = (warp & 3) * 32;
    const int nbase = (warp >> 2) * 64;

    const int row0 = blockIdx.y * 128;
    const int col0 = blockIdx.x * 128;
    const int z    = blockIdx.z;

    const __half* Bz = BhAll + (size_t)z * A_ * R_;

    const int sr  = tid >> 3;
    const int sc8 = tid & 7;
    const uint32_t smbase = smem_u32(smu);
    const uint32_t swoff  = (uint32_t)((sc8 ^ (sr & 7)) << 2);

    if (tid < 128) sred[tid] = 0.f;

    const int l15  = lane & 15;
    const int gAhi = lane >> 4;
    const int rB   = (lane & 7) + ((lane & 16) >> 1);
    const int gBlo = (lane >> 3) & 1;

    auto issue = [&](int cc) {
        if (cc < 8) {
            const int kb = cc * 64;
            const uint32_t stA = smbase + (uint32_t)(cc % 3) * (STAGE * 4);
            const uint32_t stB = stA + AW * 4;
            #pragma unroll
            for (int j = 0; j < 4; j++) {
                int r = sr + j * 32;
                cp16(stA + (r * 32) * 4 + swoff * 4,
                     Ah + (long long)(row0 + r) * 512 + kb + sc8 * 8);
                int n = col0 + r; if (n >= A_) n = A_ - 1;
                cp16(stB + (r * 32) * 4 + swoff * 4,
                     Bz + (long long)n * 512 + kb + sc8 * 8);
            }
        }
        CP_COMMIT();
    };

    float acc[2][8][4];
    #pragma unroll
    for (int mt = 0; mt < 2; mt++)
        #pragma unroll
        for (int nt = 0; nt < 8; nt++)
            #pragma unroll
            for (int q = 0; q < 4; q++) acc[mt][nt][q] = 0.f;

    issue(0);
    issue(1);

    for (int cc = 0; cc < 8; cc++) {
        CP_WAIT1();
        __syncthreads();
        issue(cc + 2);

        const uint32_t stA = smbase + (uint32_t)(cc % 3) * (STAGE * 4);
        const uint32_t stB = stA + AW * 4;

        #pragma unroll
        for (int ks = 0; ks < 4; ks++) {
            uint32_t aF[2][4];
            #pragma unroll
            for (int mt = 0; mt < 2; mt++) {
                const int rA = mbase + mt * 16 + l15;
                const uint32_t g = (uint32_t)((2 * ks + gAhi) ^ (rA & 7));
                LDSM_X4(aF[mt][0], aF[mt][1], aF[mt][2], aF[mt][3],
                        stA + (uint32_t)rA * 128 + (g << 4));
            }
            #pragma unroll
            for (int p = 0; p < 4; p++) {
                const int rBB = nbase + p * 16 + rB;
                const uint32_t g = (uint32_t)((2 * ks + gBlo) ^ (rBB & 7));
                uint32_t b0, b1, b2, b3;
                LDSM_X4(b0, b1, b2, b3, stB + (uint32_t)rBB * 128 + (g << 4));
                MMA_F16(acc[0][2 * p],     aF[0], b0, b1);
                MMA_F16(acc[1][2 * p],     aF[1], b0, b1);
                MMA_F16(acc[0][2 * p + 1], aF[0], b2, b3);
                MMA_F16(acc[1][2 * p + 1], aF[1], b2, b3);
            }
        }
    }

    const float* bz = biasAll + (size_t)z * A_;

    if (z & 1) {
        __half* Cz = Mout;
        #pragma unroll
        for (int mt = 0; mt < 2; mt++) {
            const int rlo = row0 + mbase + mt * 16 + gid;
            const int rhi = rlo + 8;
            #pragma unroll
            for (int nt = 0; nt < 8; nt++) {
                const int n0 = col0 + nbase + nt * 8 + 2 * tig;
                if (n0 >= A_) continue;
                float b0v = bz[n0], b1v = bz[n0 + 1];
                *reinterpret_cast<__half2*>(Cz + (long long)rlo * KC_ + z * A_ + n0) =
                    __floats2half2_rn(acc[mt][nt][0] + b0v, acc[mt][nt][1] + b1v);
                *reinterpret_cast<__half2*>(Cz + (long long)rhi * KC_ + z * A_ + n0) =
                    __floats2half2_rn(acc[mt][nt][2] + b0v, acc[mt][nt][3] + b1v);
            }
        }
    } else {
        const int zl = z >> 1;
        const float* hz = hh2 + (size_t)zl * BA_;
        const float* wz = wAll + (size_t)z * A_;
        __syncthreads();
        #pragma unroll
        for (int mt = 0; mt < 2; mt++) {
            const int rlo = row0 + mbase + mt * 16 + gid;
            const int rhi = rlo + 8;
            const float hl = hz[rlo], hb = hz[rhi];
            float plo = 0.f, phi = 0.f;
            #pragma unroll
            for (int nt = 0; nt < 8; nt++) {
                const int n0 = col0 + nbase + nt * 8 + 2 * tig;
                if (n0 >= A_) continue;
                const float b0v = bz[n0], b1v = bz[n0 + 1];
                const float w0v = wz[n0], w1v = wz[n0 + 1];
                float2 tl = __half22float2(htanh2(__floats2half2_rn(
                    acc[mt][nt][0] + b0v + hl, acc[mt][nt][1] + b1v + hl)));
                float2 th = __half22float2(htanh2(__floats2half2_rn(
                    acc[mt][nt][2] + b0v + hb, acc[mt][nt][3] + b1v + hb)));
                plo = fmaf(tl.x, w0v, fmaf(tl.y, w1v, plo));
                phi = fmaf(th.x, w0v, fmaf(th.y, w1v, phi));
            }
            plo += __shfl_xor_sync(0xFFFFFFFFu, plo, 1);
            plo += __shfl_xor_sync(0xFFFFFFFFu, plo, 2);
            phi += __shfl_xor_sync(0xFFFFFFFFu, phi, 1);
            phi += __shfl_xor_sync(0xFFFFFFFFu, phi, 2);
            if (tig == 0) {
                atomicAdd(&sred[mbase + mt * 16 + gid], plo);
                atomicAdd(&sred[mbase + mt * 16 + gid + 8], phi);
            }
        }
        __syncthreads();
        if (tid < 128)
            scorep[(size_t)(zl * 2 + blockIdx.x) * BA_ + row0 + tid] = sred[tid];
    }
}

// ---------------------------------------------------------------------------
// fp32 -> half conversion (guarded)
// ---------------------------------------------------------------------------
__global__ __launch_bounds__(256)
void conv_half(const float4* __restrict__ in, __half2* __restrict__ outp, int n4)
{
    const int i = blockIdx.x * 256 + threadIdx.x;
    if (i >= n4) return;
    float4 v = in[i];
    outp[2 * i]     = __floats2half2_rn(v.x, v.y);
    outp[2 * i + 1] = __floats2half2_rn(v.z, v.w);
}

// o = half(a + b)
__global__ __launch_bounds__(256)
void addconv(const float4* __restrict__ a, const float4* __restrict__ b,
             __half2* __restrict__ o)
{
    const int i = blockIdx.x * 256 + threadIdx.x;
    float4 va = a[i], vb = b[i];
    o[2 * i]     = __floats2half2_rn(va.x + vb.x, va.y + vb.y);
    o[2 * i + 1] = __floats2half2_rn(va.z + vb.z, va.w + vb.w);
}

// ---------------------------------------------------------------------------
// Score from 4 K-split hh partials + per-a bias (calls 1,3)
// ---------------------------------------------------------------------------
__global__ __launch_bounds__(256)
void score4_kernel(const __half* __restrict__ Mh, const float* __restrict__ hhp,
                   const float* __restrict__ hbias,
                   const float* __restrict__ w, const float* __restrict__ d2db,
                   float* __restrict__ score, int col_off)
{
    const int id   = blockIdx.x * 8 + (threadIdx.x >> 5);
    const int lane = threadIdx.x & 31;
    const float h  = hhp[id] + hhp[BA_ + id] + hhp[2 * BA_ + id] + hhp[3 * BA_ + id]
                   + hbias[id % A_];
    const __half2* row = reinterpret_cast<const __half2*>(
        Mh + (size_t)id * KC_ + col_off);
    const float2* w2 = reinterpret_cast<const float2*>(w);
    const __half2 h2 = __float2half2_rn(h);
    float s = 0.f;
    for (int k = lane; k < A_ / 2; k += 32) {
        float2 tf = __half22float2(htanh2(__hadd2(row[k], h2)));
        float2 ww = w2[k];
        s = fmaf(tf.x, ww.x, s);
        s = fmaf(tf.y, ww.y, s);
    }
    #pragma unroll
    for (int o = 16; o > 0; o >>= 1)
        s += __shfl_xor_sync(0xFFFFFFFFu, s, o);
    if (lane == 0) score[id] = s + d2db[0];
}

// ---------------------------------------------------------------------------
// Softmax helper from explicit logit values
// ---------------------------------------------------------------------------
__device__ __forceinline__ void softmax_vals(float l0, float l1, float* sw,
                                             float* red, int tid)
{
    const int t2 = tid + 128;
    red[tid] = fmaxf(l0, l1); __syncthreads();
    for (int s = 64; s > 0; s >>= 1) {
        if (tid < s) red[tid] = fmaxf(red[tid], red[tid + s]);
        __syncthreads();
    }
    const float mx = red[0]; __syncthreads();
    float e0 = mexp(l0 - mx);
    float e1 = (t2 < A_) ? mexp(l1 - mx) : 0.f;
    red[tid] = e0 + e1; __syncthreads();
    for (int s = 64; s > 0; s >>= 1) {
        if (tid < s) red[tid] += red[tid + s];
        __syncthreads();
    }
    const float inv = 1.f / red[0];
    sw[tid] = e0 * inv;
    if (t2 < A_) sw[t2] = e1 * inv;
    __syncthreads();
}

// ---------------------------------------------------------------------------
// Dual weighted sum from fused-score partials (calls 0,2) -> HALF att0
// ---------------------------------------------------------------------------
__global__ __launch_bounds__(128)
void wsum2_sm(const __half2* __restrict__ atth, const float* __restrict__ sp,
              const float* __restrict__ d2db, __half* __restrict__ outp)
{
    const int b   = blockIdx.y;
    const int tid = threadIdx.x;
    __shared__ float w0[A_], w1[A_];
    __shared__ float red[128];

    const int i0 = b * A_ + tid;
    const int i1 = i0 + 128;
    const bool v1 = (tid + 128) < A_;
    {
        float db = d2db[0];
        float l0 = sp[i0] + sp[BA_ + i0] + db;
        float l1 = v1 ? (sp[i1] + sp[BA_ + i1] + db) : -INFINITY;
        softmax_vals(l0, l1, w0, red, tid);
    }
    {
        float db = d2db[2];
        float l0 = sp[2 * BA_ + i0] + sp[3 * BA_ + i0] + db;
        float l1 = v1 ? (sp[2 * BA_ + i1] + sp[3 * BA_ + i1] + db) : -INFINITY;
        softmax_vals(l0, l1, w1, red, tid);
    }

    const __half2* ab = atth + (((size_t)b * A_ * R_) >> 1)
                       + (blockIdx.x * 256 >> 1) + tid;
    float ax = 0.f, ay = 0.f, bx = 0.f, by = 0.f;
    #pragma unroll 14
    for (int a = 0; a < A_; a++) {
        float2 f = __half22float2(ab[a * (R_ / 2)]);
        ax = fmaf(f.x, w0[a], ax); ay = fmaf(f.y, w0[a], ay);
        bx = fmaf(f.x, w1[a], bx); by = fmaf(f.y, w1[a], by);
    }
    const int r = blockIdx.x * 256 + tid * 2;
    *reinterpret_cast<__half2*>(outp + b * R_ + r)           = __floats2half2_rn(ax, ay);
    *reinterpret_cast<__half2*>(outp + B_ * R_ + b * R_ + r) = __floats2half2_rn(bx, by);
}

// Single weighted sum + softmax (+ addv); optional half copy of the output
__global__ __launch_bounds__(128)
void wsum_sm(const __half2* __restrict__ atth, const float* __restrict__ score,
             const float* __restrict__ addv, float* __restrict__ outp,
             __half* __restrict__ outh)
{
    const int b   = blockIdx.y;
    const int tid = threadIdx.x;
    __shared__ float w0[A_];
    __shared__ float red[128];

    const float* sc = score + b * A_;
    float l0 = sc[tid];
    float l1 = (tid + 128 < A_) ? sc[tid + 128] : -INFINITY;
    softmax_vals(l0, l1, w0, red, tid);

    const __half2* ab = atth + (((size_t)b * A_ * R_) >> 1)
                       + (blockIdx.x * 256 >> 1) + tid;
    float ax = 0.f, ay = 0.f;
    #pragma unroll 14
    for (int a = 0; a < A_; a++) {
        float2 f = __half22float2(ab[a * (R_ / 2)]);
        ax = fmaf(f.x, w0[a], ax);
        ay = fmaf(f.y, w0[a], ay);
    }
    const int r = blockIdx.x * 256 + tid * 2;
    float2 av = *reinterpret_cast<const float2*>(addv + b * R_ + r);
    ax += av.x; ay += av.y;
    *reinterpret_cast<float2*>(outp + b * R_ + r) = make_float2(ax, ay);
    if (outh)
        *reinterpret_cast<__half2*>(outh + b * R_ + r) = __floats2half2_rn(ax, ay);
}

// ---------------------------------------------------------------------------
// Gates + cell update + mean over P (float + half next_h outputs)
// ---------------------------------------------------------------------------
__global__ __launch_bounds__(256)
void gate_kernel(const float* __restrict__ sums,
                 const float* __restrict__ bi, const float* __restrict__ bh,
                 const float* __restrict__ ba,
                 const float* __restrict__ prev_c,
                 float* __restrict__ next_c, float* __restrict__ next_h,
                 __half* __restrict__ next_hh)
{
    const int idx = blockIdx.x * 256 + threadIdx.x;
    const int b = idx >> 9, r = idx & (R_ - 1);
    const float pc = prev_c[idx];
    float ca = 0.f, ha = 0.f;
    #pragma unroll
    for (int p = 0; p < P_; p++) {
        const long long base = ((long long)p * B_ + b) * G4_;
        const int bb = p * G4_;
        float si = sums[base + r]        + bi[bb + r]        + bh[bb + r]        + ba[bb + r];
        float sf = sums[base + R_ + r]   + bi[bb + R_ + r]   + bh[bb + R_ + r]   + ba[bb + R_ + r];
        float so = sums[base + 2*R_ + r] + bi[bb + 2*R_ + r] + bh[bb + 2*R_ + r] + ba[bb + 2*R_ + r];
        float st = sums[base + 3*R_ + r] + bi[bb + 3*R_ + r] + bh[bb + 3*R_ + r] + ba[bb + 3*R_ + r];
        float ig = msig(si);
        float fg = msig(sf);
        float og = msig(so);
        float it = mtanh(st);
        float nc = fg * pc + ig * it;
        ca += nc;
        ha += og * mtanh(nc);
    }
    const float hval = ha * (1.f / 3.f);
    next_c[idx]  = ca * (1.f / 3.f);
    next_h[idx]  = hval;
    next_hh[idx] = __float2half(hval);
}

// ---------------------------------------------------------------------------
// In-place log-softmax over V per row
// ---------------------------------------------------------------------------
__global__ __launch_bounds__(256)
void logsoftmax_kernel(float* __restrict__ x)
{
    const int b = blockIdx.x, tid = threadIdx.x;
    __shared__ float red[256];
    float* row = x + (long long)b * V_;

    float mx = -INFINITY;
    for (int i = tid; i < V_; i += 256) mx = fmaxf(mx, row[i]);
    red[tid] = mx; __syncthreads();
    for (int s = 128; s > 0; s >>= 1) {
        if (tid < s) red[tid] = fmaxf(red[tid], red[tid + s]);
        __syncthreads();
    }
    mx = red[0]; __syncthreads();

    float sum = 0.f;
    for (int i = tid; i < V_; i += 256) sum += mexp(row[i] - mx);
    red[tid] = sum; __syncthreads();
    for (int s = 128; s > 0; s >>= 1) {
        if (tid < s) red[tid] += red[tid + s];
        __syncthreads();
    }
    const float lz = logf(red[0]) + mx;
    for (int i = tid; i < V_; i += 256) row[i] = row[i] - lz;
}

// ---------------------------------------------------------------------------
// Host launch
// ---------------------------------------------------------------------------
extern "C" void kernel_launch(void* const* d_in, const int* in_sizes, int n_in,
                              void* d_out, int out_size)
{
    (void)in_sizes; (void)n_in; (void)out_size;
    const float* x      = (const float*)d_in[0];
    const float* att    = (const float*)d_in[1];
    const float* inputs = (const float*)d_in[2];
    const float* i2h_w  = (const float*)d_in[3];
    const float* i2h_b  = (const float*)d_in[4];
    const float* h2h_w  = (const float*)d_in[5];
    const float* h2h_b  = (const float*)d_in[6];
    const float* a2h_w  = (const float*)d_in[7];
    const float* a2h_b  = (const float*)d_in[8];
    const float* a2a_w  = (const float*)d_in[9];
    const float* a2a_b  = (const float*)d_in[10];
    const float* h2a_w  = (const float*)d_in[11];
    const float* h2a_b  = (const float*)d_in[12];
    const float* d2d_w  = (const float*)d_in[13];
    const float* d2d_b  = (const float*)d_in[14];
    const float* proj_w = (const float*)d_in[15];
    const float* proj_b = (const float*)d_in[16];
    float* out = (float*)d_out;

    __half *pMh, *patth, *pa2awh, *pi2hwh, *ph2hwh, *pa2hwh, *ph2awh, *pprojwh;
    __half *pinh, *pxth, *patt0h, *pnhh, *pthh;
    float *phh2, *phhp, *pscore, *pscorep, *psums, *pnh;
    cudaGetSymbolAddress((void**)&pMh,     gMh);
    cudaGetSymbolAddress((void**)&patth,   g_atth);
    cudaGetSymbolAddress((void**)&pa2awh,  g_a2awh);
    cudaGetSymbolAddress((void**)&pi2hwh,  g_i2hwh);
    cudaGetSymbolAddress((void**)&ph2hwh,  g_h2hwh);
    cudaGetSymbolAddress((void**)&pa2hwh,  g_a2hwh);
    cudaGetSymbolAddress((void**)&ph2awh,  g_h2awh);
    cudaGetSymbolAddress((void**)&pprojwh, g_projwh);
    cudaGetSymbolAddress((void**)&pinh,    g_inh);
    cudaGetSymbolAddress((void**)&pxth,    g_xth);
    cudaGetSymbolAddress((void**)&patt0h,  g_att0h);
    cudaGetSymbolAddress((void**)&pnhh,    g_nhh);
    cudaGetSymbolAddress((void**)&pthh,    g_thh);
    cudaGetSymbolAddress((void**)&phh2,    g_hh2);
    cudaGetSymbolAddress((void**)&phhp,    g_hhp);
    cudaGetSymbolAddress((void**)&pscore,  g_score);
    cudaGetSymbolAddress((void**)&pscorep, g_scorep);
    cudaGetSymbolAddress((void**)&psums,   g_sums);
    cudaGetSymbolAddress((void**)&pnh,     g_nh);

    static bool attr_done = false;
    const int smemS  = 3 * (128 + 128) * 32 * 4;   // 98304 (gemm_f16s)
    const int smemH  = 3 * (128 + 64)  * 32 * 4;   // 73728 (gemm_f16h<64>)
    if (!attr_done) {
        cudaFuncSetAttribute(gemm_f16s,     cudaFuncAttributeMaxDynamicSharedMemorySize, smemS);
        cudaFuncSetAttribute(gemm_f16h<64>, cudaFuncAttributeMaxDynamicSharedMemorySize, smemH);
        cudaFuncSetAttribute(gemm_f16s,
                             cudaFuncAttributePreferredSharedMemoryCarveout, 100);
        cudaFuncSetAttribute(gemm_f16h<64>,
                             cudaFuncAttributePreferredSharedMemoryCarveout, 100);
        attr_done = true;
    }

    dim3 blk(256);
    const size_t wst = (size_t)G4_ * R_;   // per-p weight stride (elements/halves)
    const __half2* atth2 = reinterpret_cast<const __half2*>(patth);

    auto CV = [&](const float* src, __half* dst, size_t n) {
        int n4 = (int)(n / 4);
        conv_half<<<(n4 + 255) / 256, blk>>>(
            reinterpret_cast<const float4*>(src),
            reinterpret_cast<__half2*>(dst), n4);
    };

    // 0) all fp32->half conversions (DRAM-neutral vs fp32 GEMM reads)
    CV(att,    patth,   (size_t)B_ * A_ * R_);
    CV(a2a_w,  pa2awh,  (size_t)KC_ * R_);
    CV(i2h_w,  pi2hwh,  (size_t)L_ * P_ * G4_ * R_);
    CV(h2h_w,  ph2hwh,  (size_t)L_ * P_ * G4_ * R_);
    CV(a2h_w,  pa2hwh,  (size_t)L_ * P_ * G4_ * R_);
    CV(h2a_w,  ph2awh,  (size_t)L_ * 2 * A_ * R_);
    CV(proj_w, pprojwh, (size_t)V_ * R_);
    CV(inputs + (size_t)B_ * R_,     pinh,               (size_t)B_ * R_);
    CV(inputs + (size_t)3 * B_ * R_, pinh + (size_t)B_ * R_, (size_t)B_ * R_);
    CV(x,      pxth,    (size_t)B_ * R_);

    // 1) hh2 for call0 of both layers (z = layer), f16
    gemm_f16h<64><<<dim3(4, 2, 2), blk, smemH>>>(
        pinh, pinh, pinh, ph2awh, ph2awh, ph2awh, phh2, h2a_b,
        A_, R_, A_,
        (long long)B_ * R_, (long long)2 * A_ * R_,
        (long long)BA_, (long long)2 * A_);

    // 2) merged f16 logits GEMM: fused score (calls 0,2) + logits out (1,3)
    gemm_f16s<<<dim3(2, BA_ / 128, 4), blk, smemS>>>(
        patth, pa2awh, a2a_b, phh2, d2d_w, pMh, pscorep);

    // 3) att_res0 for both layers (half output for gate GEMM)
    wsum2_sm<<<dim3(R_ / 256, B_), dim3(128)>>>(atth2, pscorep, d2d_b, patt0h);

    for (int i = 0; i < L_; i++) {
        const float* prev_c = inputs + (size_t)(2 * i) * B_ * R_;
        const int c1 = 2 * i + 1;

        if (i == 1) {
            addconv<<<(B_ * R_) / 4 / 256, blk>>>(
                reinterpret_cast<const float4*>(x),
                reinterpret_cast<const float4*>(out + (size_t)1 * B_ * R_),
                reinterpret_cast<__half2*>(pxth));
        }

        // fused gate GEMM (f16): K=1536, A segs [xt, prev_h, att0_i]
        gemm_f16h<64><<<dim3(32, 2, P_), blk, smemH>>>(
            pxth, pinh + (size_t)i * B_ * R_, patt0h + (size_t)i * B_ * R_,
            pi2hwh + (size_t)i * P_ * wst,
            ph2hwh + (size_t)i * P_ * wst,
            pa2hwh + (size_t)i * P_ * wst,
            psums, nullptr,
            G4_, 3 * R_, G4_,
            0, (long long)wst, (long long)B_ * G4_, 0);

        gate_kernel<<<(B_ * R_) / 256, blk>>>(
            psums,
            i2h_b + (size_t)i * P_ * G4_,
            h2h_b + (size_t)i * P_ * G4_,
            a2h_b + (size_t)i * P_ * G4_,
            prev_c,
            out + (size_t)(2 * i) * B_ * R_, pnh, pnhh);

        // call1 hh: K-split x4 into partials (z = k-slice of 128 halves)
        {
            const __half* bw = ph2awh + (size_t)c1 * A_ * R_;
            gemm_f16h<64><<<dim3(4, 2, 4), blk, smemH>>>(
                pnhh, pnhh, pnhh, bw, bw, bw, phhp, nullptr,
                A_, 128, A_,
                128, 128, (long long)BA_, 0);
        }
        score4_kernel<<<BA_ / 8, blk>>>(pMh, phhp, h2a_b + (size_t)c1 * A_,
                                        d2d_w + (size_t)c1 * A_, d2d_b + c1,
                                        pscore, c1 * A_);
        wsum_sm<<<dim3(R_ / 256, B_), dim3(128)>>>(
            atth2, pscore, pnh, out + (size_t)(2 * i + 1) * B_ * R_,
            (i == 1) ? pthh : (__half*)nullptr);
    }

    // projection (f16) + log-softmax
    gemm_f16h<64><<<dim3((V_ + 63) / 64, 2, 1), blk, smemH>>>(
        pthh, pthh, pthh, pprojwh, pprojwh, pprojwh,
        out + (size_t)4 * B_ * R_, proj_b,
        V_, R_, V_, 0, 0, 0, 0);
    logsoftmax_kernel<<<B_, blk>>>(out + (size_t)4 * B_ * R_);
}

// round 12
// speedup vs baseline: 1.0958x; 1.0180x over previous
#include <cuda_runtime.h>
#include <cuda_fp16.h>
#include <math.h>
#include <stdint.h>

// Problem constants
#define L_   2
#define P_   3
#define R_   512
#define A_   196
#define V_   9487
#define B_   256
#define BA_  (B_*A_)        // 50176
#define KC_  (2*L_*A_)      // 784
#define G4_  (4*R_)         // 2048

// ---------------------------------------------------------------------------
// Static device scratch (allocation-free)
// ---------------------------------------------------------------------------
__device__ __half gMh    [(size_t)BA_ * KC_];     // logits half (calls 1,3 cols)
__device__ __half g_atth [(size_t)B_ * A_ * R_];  // att half
__device__ __half g_a2awh[(size_t)KC_ * R_];
__device__ __half g_i2hwh[(size_t)L_ * P_ * G4_ * R_];
__device__ __half g_h2hwh[(size_t)L_ * P_ * G4_ * R_];
__device__ __half g_a2hwh[(size_t)L_ * P_ * G4_ * R_];
__device__ __half g_h2awh[(size_t)L_ * 2 * A_ * R_];
__device__ __half g_projwh[(size_t)V_ * R_];
__device__ __half g_inh  [2 * B_ * R_];           // prev_h of both layers, half
__device__ __half g_xth  [B_ * R_];
__device__ __half g_att0h[2 * B_ * R_];
__device__ __half g_nhh  [B_ * R_];
__device__ __half g_thh  [B_ * R_];               // top_h layer1, half
__device__ float g_hh2  [2 * B_ * A_];
__device__ float g_hhp  [4 * B_ * A_];
__device__ float g_score[BA_];
__device__ float g_scorep[4 * BA_];
__device__ float g_sums [P_ * B_ * G4_];
__device__ float g_nh   [B_ * R_];

// ---------------------------------------------------------------------------
// Streams/events (created at init; capture-legal fork/join, proven in R5)
// ---------------------------------------------------------------------------
struct AsyncCtx {
    cudaStream_t s1;
    cudaEvent_t evFork, evConv;
    AsyncCtx() {
        cudaStreamCreateWithFlags(&s1, cudaStreamNonBlocking);
        cudaEventCreateWithFlags(&evFork, cudaEventDisableTiming);
        cudaEventCreateWithFlags(&evConv, cudaEventDisableTiming);
    }
};
static AsyncCtx g_async;

// ---------------------------------------------------------------------------
// MUFU-based activations
// ---------------------------------------------------------------------------
__device__ __forceinline__ float mexp(float x) {
    float r;
    asm("ex2.approx.f32 %0, %1;" : "=f"(r) : "f"(x * 1.4426950408889634f));
    return r;
}
__device__ __forceinline__ float msig(float x) {
    float t = fminf(-1.4426950408889634f * x, 126.0f);
    float u;
    asm("ex2.approx.f32 %0, %1;" : "=f"(u) : "f"(t));
    float d = 1.0f + u;
    float r;
    asm("rcp.approx.f32 %0, %1;" : "=f"(r) : "f"(d));
    r = r * fmaf(-d, r, 2.0f);
    return r;
}
__device__ __forceinline__ float mtanh(float x) {
    return fmaf(2.0f, msig(2.0f * x), -1.0f);
}
__device__ __forceinline__ __half2 htanh2(__half2 v) {
    uint32_t vi = *reinterpret_cast<uint32_t*>(&v);
    uint32_t to;
    asm("tanh.approx.f16x2 %0, %1;" : "=r"(to) : "r"(vi));
    return *reinterpret_cast<__half2*>(&to);
}

// ---------------------------------------------------------------------------
// mma / cp.async / ldmatrix helpers
// ---------------------------------------------------------------------------
#define MMA_F16(c, a, b0, b1) \
    asm volatile("mma.sync.aligned.m16n8k16.row.col.f32.f16.f16.f32 " \
        "{%0,%1,%2,%3}, {%4,%5,%6,%7}, {%8,%9}, {%0,%1,%2,%3};" \
        : "+f"((c)[0]), "+f"((c)[1]), "+f"((c)[2]), "+f"((c)[3]) \
        : "r"((a)[0]), "r"((a)[1]), "r"((a)[2]), "r"((a)[3]), \
          "r"(b0), "r"(b1))

#define LDSM_X4(r0, r1, r2, r3, addr) \
    asm volatile("ldmatrix.sync.aligned.m8n8.x4.shared.b16 {%0,%1,%2,%3}, [%4];" \
        : "=r"(r0), "=r"(r1), "=r"(r2), "=r"(r3) : "r"(addr))

__device__ __forceinline__ uint32_t smem_u32(const void* p) {
    uint32_t a;
    asm("{ .reg .u64 t; cvta.to.shared.u64 t, %1; cvt.u32.u64 %0, t; }" : "=r"(a) : "l"(p));
    return a;
}
__device__ __forceinline__ void cp16(uint32_t dst, const void* src) {
    asm volatile("cp.async.cg.shared.global [%0], [%1], 16;" :: "r"(dst), "l"(src));
}
#define CP_COMMIT() asm volatile("cp.async.commit_group;" ::: "memory")
#define CP_WAIT1()  asm volatile("cp.async.wait_group 1;" ::: "memory")

// ---------------------------------------------------------------------------
// Generic f16 NT GEMM, fp32 out (unchanged from R11)
// ---------------------------------------------------------------------------
template<int BN>
__global__ __launch_bounds__(256, 2)
void gemm_f16h(const __half* __restrict__ A0, const __half* __restrict__ A1,
               const __half* __restrict__ A2,
               const __half* __restrict__ B0, const __half* __restrict__ B1,
               const __half* __restrict__ B2,
               float* __restrict__ C, const float* __restrict__ bias,
               int N, int Ktot, int ldc,
               long long sA, long long sB, long long sC, long long sBias)
{
    constexpr int NT    = BN / 16;
    constexpr int AWu   = 128 * 32;
    constexpr int BWu   = BN * 32;
    constexpr int STAGE = AWu + BWu;

    extern __shared__ uint32_t smu[];

    const int tid   = threadIdx.x;
    const int warp  = tid >> 5;
    const int lane  = tid & 31;
    const int gid   = lane >> 2;
    const int tig   = lane & 3;
    const int mbase = (warp & 3) * 32;
    const int nbase = (warp >> 2) * (BN / 2);

    const int row0 = blockIdx.y * 128;
    const int col0 = blockIdx.x * BN;
    const int z    = blockIdx.z;

    const int sr  = tid >> 3;
    const int sc8 = tid & 7;
    const uint32_t smbase = smem_u32(smu);
    const uint32_t swoff  = (uint32_t)((sc8 ^ (sr & 7)) << 2);

    const int l15  = lane & 15;
    const int gAhi = lane >> 4;
    const int rB   = (lane & 7) + ((lane & 16) >> 1);
    const int gBlo = (lane >> 3) & 1;

    const int ncc = Ktot >> 6;

    auto issue = [&](int cc) {
        if (cc < ncc) {
            const int kb  = cc << 6;
            const int seg = kb >> 9;
            const int kbl = kb & 511;
            const __half* Ap = ((seg == 0) ? A0 : (seg == 1) ? A1 : A2)
                               + (long long)z * sA + kbl + sc8 * 8;
            const __half* Bp = ((seg == 0) ? B0 : (seg == 1) ? B1 : B2)
                               + (long long)z * sB + kbl + sc8 * 8;
            const uint32_t stA = smbase + (uint32_t)(cc % 3) * (STAGE * 4);
            const uint32_t stB = stA + AWu * 4;
            #pragma unroll
            for (int j = 0; j < 4; j++) {
                int r = sr + j * 32;
                cp16(stA + (r * 32) * 4 + swoff * 4,
                     Ap + (long long)(row0 + r) * 512);
            }
            #pragma unroll
            for (int j = 0; j < BN / 32; j++) {
                int r = sr + j * 32;
                int n = col0 + r; if (n >= N) n = N - 1;
                cp16(stB + (r * 32) * 4 + swoff * 4,
                     Bp + (long long)n * 512);
            }
        }
        CP_COMMIT();
    };

    float acc[2][NT][4];
    #pragma unroll
    for (int mt = 0; mt < 2; mt++)
        #pragma unroll
        for (int nt = 0; nt < NT; nt++)
            #pragma unroll
            for (int q = 0; q < 4; q++) acc[mt][nt][q] = 0.f;

    issue(0);
    issue(1);

    for (int cc = 0; cc < ncc; cc++) {
        CP_WAIT1();
        __syncthreads();
        issue(cc + 2);

        const uint32_t stA = smbase + (uint32_t)(cc % 3) * (STAGE * 4);
        const uint32_t stB = stA + AWu * 4;

        #pragma unroll
        for (int ks = 0; ks < 4; ks++) {
            uint32_t aF[2][4];
            #pragma unroll
            for (int mt = 0; mt < 2; mt++) {
                const int rA = mbase + mt * 16 + l15;
                const uint32_t g = (uint32_t)((2 * ks + gAhi) ^ (rA & 7));
                LDSM_X4(aF[mt][0], aF[mt][1], aF[mt][2], aF[mt][3],
                        stA + (uint32_t)rA * 128 + (g << 4));
            }
            #pragma unroll
            for (int p = 0; p < BN / 32; p++) {
                const int rBB = nbase + p * 16 + rB;
                const uint32_t g = (uint32_t)((2 * ks + gBlo) ^ (rBB & 7));
                uint32_t b0, b1, b2, b3;
                LDSM_X4(b0, b1, b2, b3, stB + (uint32_t)rBB * 128 + (g << 4));
                MMA_F16(acc[0][2 * p],     aF[0], b0, b1);
                MMA_F16(acc[1][2 * p],     aF[1], b0, b1);
                MMA_F16(acc[0][2 * p + 1], aF[0], b2, b3);
                MMA_F16(acc[1][2 * p + 1], aF[1], b2, b3);
            }
        }
    }

    float* Cz = C + (long long)z * sC;
    const float* bz = bias ? (bias + (long long)z * sBias) : nullptr;
    const bool even = ((ldc & 1) == 0);
    #pragma unroll
    for (int mt = 0; mt < 2; mt++) {
        const int rlo = row0 + mbase + mt * 16 + gid;
        const int rhi = rlo + 8;
        #pragma unroll
        for (int nt = 0; nt < NT; nt++) {
            const int n0 = col0 + nbase + nt * 8 + 2 * tig;
            if (n0 >= N) continue;
            float b0v = bz ? bz[n0] : 0.f;
            float b1v = (bz && n0 + 1 < N) ? bz[n0 + 1] : 0.f;
            float c0 = acc[mt][nt][0] + b0v;
            float c1 = acc[mt][nt][1] + b1v;
            float c2 = acc[mt][nt][2] + b0v;
            float c3 = acc[mt][nt][3] + b1v;
            if (even && (n0 + 1 < N)) {
                *reinterpret_cast<float2*>(Cz + (long long)rlo * ldc + n0) = make_float2(c0, c1);
                *reinterpret_cast<float2*>(Cz + (long long)rhi * ldc + n0) = make_float2(c2, c3);
            } else {
                Cz[(long long)rlo * ldc + n0] = c0;
                Cz[(long long)rhi * ldc + n0] = c2;
                if (n0 + 1 < N) {
                    Cz[(long long)rlo * ldc + n0 + 1] = c1;
                    Cz[(long long)rhi * ldc + n0 + 1] = c3;
                }
            }
        }
    }
}

// ---------------------------------------------------------------------------
// Merged f16 logits GEMM (unchanged): fused score (z even) / logits out (z odd)
// ---------------------------------------------------------------------------
__global__ __launch_bounds__(256, 2)
void gemm_f16s(const __half* __restrict__ Ah, const __half* __restrict__ BhAll,
               const float* __restrict__ biasAll, const float* __restrict__ hh2,
               const float* __restrict__ wAll,
               __half* __restrict__ Mout, float* __restrict__ scorep)
{
    constexpr int AW    = 128 * 32;
    constexpr int STAGE = AW + AW;

    extern __shared__ uint32_t smu[];
    __shared__ float sred[128];

    const int tid   = threadIdx.x;
    const int warp  = tid >> 5;
    const int lane  = tid & 31;
    const int gid   = lane >> 2;
    const int tig   = lane & 3;
    const int mbase = (warp & 3) * 32;
    const int nbase = (warp >> 2) * 64;

    const int row0 = blockIdx.y * 128;
    const int col0 = blockIdx.x * 128;
    const int z    = blockIdx.z;

    const __half* Bz = BhAll + (size_t)z * A_ * R_;

    const int sr  = tid >> 3;
    const int sc8 = tid & 7;
    const uint32_t smbase = smem_u32(smu);
    const uint32_t swoff  = (uint32_t)((sc8 ^ (sr & 7)) << 2);

    if (tid < 128) sred[tid] = 0.f;

    const int l15  = lane & 15;
    const int gAhi = lane >> 4;
    const int rB   = (lane & 7) + ((lane & 16) >> 1);
    const int gBlo = (lane >> 3) & 1;

    auto issue = [&](int cc) {
        if (cc < 8) {
            const int kb = cc * 64;
            const uint32_t stA = smbase + (uint32_t)(cc % 3) * (STAGE * 4);
            const uint32_t stB = stA + AW * 4;
            #pragma unroll
            for (int j = 0; j < 4; j++) {
                int r = sr + j * 32;
                cp16(stA + (r * 32) * 4 + swoff * 4,
                     Ah + (long long)(row0 + r) * 512 + kb + sc8 * 8);
                int n = col0 + r; if (n >= A_) n = A_ - 1;
                cp16(stB + (r * 32) * 4 + swoff * 4,
                     Bz + (long long)n * 512 + kb + sc8 * 8);
            }
        }
        CP_COMMIT();
    };

    float acc[2][8][4];
    #pragma unroll
    for (int mt = 0; mt < 2; mt++)
        #pragma unroll
        for (int nt = 0; nt < 8; nt++)
            #pragma unroll
            for (int q = 0; q < 4; q++) acc[mt][nt][q] = 0.f;

    issue(0);
    issue(1);

    for (int cc = 0; cc < 8; cc++) {
        CP_WAIT1();
        __syncthreads();
        issue(cc + 2);

        const uint32_t stA = smbase + (uint32_t)(cc % 3) * (STAGE * 4);
        const uint32_t stB = stA + AW * 4;

        #pragma unroll
        for (int ks = 0; ks < 4; ks++) {
            uint32_t aF[2][4];
            #pragma unroll
            for (int mt = 0; mt < 2; mt++) {
                const int rA = mbase + mt * 16 + l15;
                const uint32_t g = (uint32_t)((2 * ks + gAhi) ^ (rA & 7));
                LDSM_X4(aF[mt][0], aF[mt][1], aF[mt][2], aF[mt][3],
                        stA + (uint32_t)rA * 128 + (g << 4));
            }
            #pragma unroll
            for (int p = 0; p < 4; p++) {
                const int rBB = nbase + p * 16 + rB;
                const uint32_t g = (uint32_t)((2 * ks + gBlo) ^ (rBB & 7));
                uint32_t b0, b1, b2, b3;
                LDSM_X4(b0, b1, b2, b3, stB + (uint32_t)rBB * 128 + (g << 4));
                MMA_F16(acc[0][2 * p],     aF[0], b0, b1);
                MMA_F16(acc[1][2 * p],     aF[1], b0, b1);
                MMA_F16(acc[0][2 * p + 1], aF[0], b2, b3);
                MMA_F16(acc[1][2 * p + 1], aF[1], b2, b3);
            }
        }
    }

    const float* bz = biasAll + (size_t)z * A_;

    if (z & 1) {
        __half* Cz = Mout;
        #pragma unroll
        for (int mt = 0; mt < 2; mt++) {
            const int rlo = row0 + mbase + mt * 16 + gid;
            const int rhi = rlo + 8;
            #pragma unroll
            for (int nt = 0; nt < 8; nt++) {
                const int n0 = col0 + nbase + nt * 8 + 2 * tig;
                if (n0 >= A_) continue;
                float b0v = bz[n0], b1v = bz[n0 + 1];
                *reinterpret_cast<__half2*>(Cz + (long long)rlo * KC_ + z * A_ + n0) =
                    __floats2half2_rn(acc[mt][nt][0] + b0v, acc[mt][nt][1] + b1v);
                *reinterpret_cast<__half2*>(Cz + (long long)rhi * KC_ + z * A_ + n0) =
                    __floats2half2_rn(acc[mt][nt][2] + b0v, acc[mt][nt][3] + b1v);
            }
        }
    } else {
        const int zl = z >> 1;
        const float* hz = hh2 + (size_t)zl * BA_;
        const float* wz = wAll + (size_t)z * A_;
        __syncthreads();
        #pragma unroll
        for (int mt = 0; mt < 2; mt++) {
            const int rlo = row0 + mbase + mt * 16 + gid;
            const int rhi = rlo + 8;
            const float hl = hz[rlo], hb = hz[rhi];
            float plo = 0.f, phi = 0.f;
            #pragma unroll
            for (int nt = 0; nt < 8; nt++) {
                const int n0 = col0 + nbase + nt * 8 + 2 * tig;
                if (n0 >= A_) continue;
                const float b0v = bz[n0], b1v = bz[n0 + 1];
                const float w0v = wz[n0], w1v = wz[n0 + 1];
                float2 tl = __half22float2(htanh2(__floats2half2_rn(
                    acc[mt][nt][0] + b0v + hl, acc[mt][nt][1] + b1v + hl)));
                float2 th = __half22float2(htanh2(__floats2half2_rn(
                    acc[mt][nt][2] + b0v + hb, acc[mt][nt][3] + b1v + hb)));
                plo = fmaf(tl.x, w0v, fmaf(tl.y, w1v, plo));
                phi = fmaf(th.x, w0v, fmaf(th.y, w1v, phi));
            }
            plo += __shfl_xor_sync(0xFFFFFFFFu, plo, 1);
            plo += __shfl_xor_sync(0xFFFFFFFFu, plo, 2);
            phi += __shfl_xor_sync(0xFFFFFFFFu, phi, 1);
            phi += __shfl_xor_sync(0xFFFFFFFFu, phi, 2);
            if (tig == 0) {
                atomicAdd(&sred[mbase + mt * 16 + gid], plo);
                atomicAdd(&sred[mbase + mt * 16 + gid + 8], phi);
            }
        }
        __syncthreads();
        if (tid < 128)
            scorep[(size_t)(zl * 2 + blockIdx.x) * BA_ + row0 + tid] = sred[tid];
    }
}

// ---------------------------------------------------------------------------
// fp32 -> half conversion (2 float4 per thread for MLP)
// ---------------------------------------------------------------------------
__global__ __launch_bounds__(256)
void conv_half(const float4* __restrict__ in, __half2* __restrict__ outp, int n4)
{
    const int i0 = blockIdx.x * 512 + threadIdx.x;
    const int i1 = i0 + 256;
    if (i0 < n4) {
        float4 v = in[i0];
        outp[2 * i0]     = __floats2half2_rn(v.x, v.y);
        outp[2 * i0 + 1] = __floats2half2_rn(v.z, v.w);
    }
    if (i1 < n4) {
        float4 v = in[i1];
        outp[2 * i1]     = __floats2half2_rn(v.x, v.y);
        outp[2 * i1 + 1] = __floats2half2_rn(v.z, v.w);
    }
}

// o = half(a + b)
__global__ __launch_bounds__(256)
void addconv(const float4* __restrict__ a, const float4* __restrict__ b,
             __half2* __restrict__ o)
{
    const int i = blockIdx.x * 256 + threadIdx.x;
    float4 va = a[i], vb = b[i];
    o[2 * i]     = __floats2half2_rn(va.x + vb.x, va.y + vb.y);
    o[2 * i + 1] = __floats2half2_rn(va.z + vb.z, va.w + vb.w);
}

// ---------------------------------------------------------------------------
// Score from 4 K-split hh partials + per-a bias (calls 1,3)
// ---------------------------------------------------------------------------
__global__ __launch_bounds__(256)
void score4_kernel(const __half* __restrict__ Mh, const float* __restrict__ hhp,
                   const float* __restrict__ hbias,
                   const float* __restrict__ w, const float* __restrict__ d2db,
                   float* __restrict__ score, int col_off)
{
    const int id   = blockIdx.x * 8 + (threadIdx.x >> 5);
    const int lane = threadIdx.x & 31;
    const float h  = hhp[id] + hhp[BA_ + id] + hhp[2 * BA_ + id] + hhp[3 * BA_ + id]
                   + hbias[id % A_];
    const __half2* row = reinterpret_cast<const __half2*>(
        Mh + (size_t)id * KC_ + col_off);
    const float2* w2 = reinterpret_cast<const float2*>(w);
    const __half2 h2 = __float2half2_rn(h);
    float s = 0.f;
    for (int k = lane; k < A_ / 2; k += 32) {
        float2 tf = __half22float2(htanh2(__hadd2(row[k], h2)));
        float2 ww = w2[k];
        s = fmaf(tf.x, ww.x, s);
        s = fmaf(tf.y, ww.y, s);
    }
    #pragma unroll
    for (int o = 16; o > 0; o >>= 1)
        s += __shfl_xor_sync(0xFFFFFFFFu, s, o);
    if (lane == 0) score[id] = s + d2db[0];
}

// ---------------------------------------------------------------------------
// Softmax helper from explicit logit values
// ---------------------------------------------------------------------------
__device__ __forceinline__ void softmax_vals(float l0, float l1, float* sw,
                                             float* red, int tid)
{
    const int t2 = tid + 128;
    red[tid] = fmaxf(l0, l1); __syncthreads();
    for (int s = 64; s > 0; s >>= 1) {
        if (tid < s) red[tid] = fmaxf(red[tid], red[tid + s]);
        __syncthreads();
    }
    const float mx = red[0]; __syncthreads();
    float e0 = mexp(l0 - mx);
    float e1 = (t2 < A_) ? mexp(l1 - mx) : 0.f;
    red[tid] = e0 + e1; __syncthreads();
    for (int s = 64; s > 0; s >>= 1) {
        if (tid < s) red[tid] += red[tid + s];
        __syncthreads();
    }
    const float inv = 1.f / red[0];
    sw[tid] = e0 * inv;
    if (t2 < A_) sw[t2] = e1 * inv;
    __syncthreads();
}

// ---------------------------------------------------------------------------
// Dual weighted sum from fused-score partials (calls 0,2) -> HALF att0
// ---------------------------------------------------------------------------
__global__ __launch_bounds__(128)
void wsum2_sm(const __half2* __restrict__ atth, const float* __restrict__ sp,
              const float* __restrict__ d2db, __half* __restrict__ outp)
{
    const int b   = blockIdx.y;
    const int tid = threadIdx.x;
    __shared__ float w0[A_], w1[A_];
    __shared__ float red[128];

    const int i0 = b * A_ + tid;
    const int i1 = i0 + 128;
    const bool v1 = (tid + 128) < A_;
    {
        float db = d2db[0];
        float l0 = sp[i0] + sp[BA_ + i0] + db;
        float l1 = v1 ? (sp[i1] + sp[BA_ + i1] + db) : -INFINITY;
        softmax_vals(l0, l1, w0, red, tid);
    }
    {
        float db = d2db[2];
        float l0 = sp[2 * BA_ + i0] + sp[3 * BA_ + i0] + db;
        float l1 = v1 ? (sp[2 * BA_ + i1] + sp[3 * BA_ + i1] + db) : -INFINITY;
        softmax_vals(l0, l1, w1, red, tid);
    }

    const __half2* ab = atth + (((size_t)b * A_ * R_) >> 1)
                       + (blockIdx.x * 256 >> 1) + tid;
    float ax = 0.f, ay = 0.f, bx = 0.f, by = 0.f;
    #pragma unroll 14
    for (int a = 0; a < A_; a++) {
        float2 f = __half22float2(ab[a * (R_ / 2)]);
        ax = fmaf(f.x, w0[a], ax); ay = fmaf(f.y, w0[a], ay);
        bx = fmaf(f.x, w1[a], bx); by = fmaf(f.y, w1[a], by);
    }
    const int r = blockIdx.x * 256 + tid * 2;
    *reinterpret_cast<__half2*>(outp + b * R_ + r)           = __floats2half2_rn(ax, ay);
    *reinterpret_cast<__half2*>(outp + B_ * R_ + b * R_ + r) = __floats2half2_rn(bx, by);
}

// Single weighted sum + softmax (+ addv); optional half copy of the output
__global__ __launch_bounds__(128)
void wsum_sm(const __half2* __restrict__ atth, const float* __restrict__ score,
             const float* __restrict__ addv, float* __restrict__ outp,
             __half* __restrict__ outh)
{
    const int b   = blockIdx.y;
    const int tid = threadIdx.x;
    __shared__ float w0[A_];
    __shared__ float red[128];

    const float* sc = score + b * A_;
    float l0 = sc[tid];
    float l1 = (tid + 128 < A_) ? sc[tid + 128] : -INFINITY;
    softmax_vals(l0, l1, w0, red, tid);

    const __half2* ab = atth + (((size_t)b * A_ * R_) >> 1)
                       + (blockIdx.x * 256 >> 1) + tid;
    float ax = 0.f, ay = 0.f;
    #pragma unroll 14
    for (int a = 0; a < A_; a++) {
        float2 f = __half22float2(ab[a * (R_ / 2)]);
        ax = fmaf(f.x, w0[a], ax);
        ay = fmaf(f.y, w0[a], ay);
    }
    const int r = blockIdx.x * 256 + tid * 2;
    float2 av = *reinterpret_cast<const float2*>(addv + b * R_ + r);
    ax += av.x; ay += av.y;
    *reinterpret_cast<float2*>(outp + b * R_ + r) = make_float2(ax, ay);
    if (outh)
        *reinterpret_cast<__half2*>(outh + b * R_ + r) = __floats2half2_rn(ax, ay);
}

// ---------------------------------------------------------------------------
// Gates + cell update + mean over P (float + half next_h outputs)
// ---------------------------------------------------------------------------
__global__ __launch_bounds__(256)
void gate_kernel(const float* __restrict__ sums,
                 const float* __restrict__ bi, const float* __restrict__ bh,
                 const float* __restrict__ ba,
                 const float* __restrict__ prev_c,
                 float* __restrict__ next_c, float* __restrict__ next_h,
                 __half* __restrict__ next_hh)
{
    const int idx = blockIdx.x * 256 + threadIdx.x;
    const int b = idx >> 9, r = idx & (R_ - 1);
    const float pc = prev_c[idx];
    float ca = 0.f, ha = 0.f;
    #pragma unroll
    for (int p = 0; p < P_; p++) {
        const long long base = ((long long)p * B_ + b) * G4_;
        const int bb = p * G4_;
        float si = sums[base + r]        + bi[bb + r]        + bh[bb + r]        + ba[bb + r];
        float sf = sums[base + R_ + r]   + bi[bb + R_ + r]   + bh[bb + R_ + r]   + ba[bb + R_ + r];
        float so = sums[base + 2*R_ + r] + bi[bb + 2*R_ + r] + bh[bb + 2*R_ + r] + ba[bb + 2*R_ + r];
        float st = sums[base + 3*R_ + r] + bi[bb + 3*R_ + r] + bh[bb + 3*R_ + r] + ba[bb + 3*R_ + r];
        float ig = msig(si);
        float fg = msig(sf);
        float og = msig(so);
        float it = mtanh(st);
        float nc = fg * pc + ig * it;
        ca += nc;
        ha += og * mtanh(nc);
    }
    const float hval = ha * (1.f / 3.f);
    next_c[idx]  = ca * (1.f / 3.f);
    next_h[idx]  = hval;
    next_hh[idx] = __float2half(hval);
}

// ---------------------------------------------------------------------------
// In-place log-softmax over V per row
// ---------------------------------------------------------------------------
__global__ __launch_bounds__(256)
void logsoftmax_kernel(float* __restrict__ x)
{
    const int b = blockIdx.x, tid = threadIdx.x;
    __shared__ float red[256];
    float* row = x + (long long)b * V_;

    float mx = -INFINITY;
    for (int i = tid; i < V_; i += 256) mx = fmaxf(mx, row[i]);
    red[tid] = mx; __syncthreads();
    for (int s = 128; s > 0; s >>= 1) {
        if (tid < s) red[tid] = fmaxf(red[tid], red[tid + s]);
        __syncthreads();
    }
    mx = red[0]; __syncthreads();

    float sum = 0.f;
    for (int i = tid; i < V_; i += 256) sum += mexp(row[i] - mx);
    red[tid] = sum; __syncthreads();
    for (int s = 128; s > 0; s >>= 1) {
        if (tid < s) red[tid] += red[tid + s];
        __syncthreads();
    }
    const float lz = logf(red[0]) + mx;
    for (int i = tid; i < V_; i += 256) row[i] = row[i] - lz;
}

// ---------------------------------------------------------------------------
// Host launch
// ---------------------------------------------------------------------------
extern "C" void kernel_launch(void* const* d_in, const int* in_sizes, int n_in,
                              void* d_out, int out_size)
{
    (void)in_sizes; (void)n_in; (void)out_size;
    const float* x      = (const float*)d_in[0];
    const float* att    = (const float*)d_in[1];
    const float* inputs = (const float*)d_in[2];
    const float* i2h_w  = (const float*)d_in[3];
    const float* i2h_b  = (const float*)d_in[4];
    const float* h2h_w  = (const float*)d_in[5];
    const float* h2h_b  = (const float*)d_in[6];
    const float* a2h_w  = (const float*)d_in[7];
    const float* a2h_b  = (const float*)d_in[8];
    const float* a2a_w  = (const float*)d_in[9];
    const float* a2a_b  = (const float*)d_in[10];
    const float* h2a_w  = (const float*)d_in[11];
    const float* h2a_b  = (const float*)d_in[12];
    const float* d2d_w  = (const float*)d_in[13];
    const float* d2d_b  = (const float*)d_in[14];
    const float* proj_w = (const float*)d_in[15];
    const float* proj_b = (const float*)d_in[16];
    float* out = (float*)d_out;

    __half *pMh, *patth, *pa2awh, *pi2hwh, *ph2hwh, *pa2hwh, *ph2awh, *pprojwh;
    __half *pinh, *pxth, *patt0h, *pnhh, *pthh;
    float *phh2, *phhp, *pscore, *pscorep, *psums, *pnh;
    cudaGetSymbolAddress((void**)&pMh,     gMh);
    cudaGetSymbolAddress((void**)&patth,   g_atth);
    cudaGetSymbolAddress((void**)&pa2awh,  g_a2awh);
    cudaGetSymbolAddress((void**)&pi2hwh,  g_i2hwh);
    cudaGetSymbolAddress((void**)&ph2hwh,  g_h2hwh);
    cudaGetSymbolAddress((void**)&pa2hwh,  g_a2hwh);
    cudaGetSymbolAddress((void**)&ph2awh,  g_h2awh);
    cudaGetSymbolAddress((void**)&pprojwh, g_projwh);
    cudaGetSymbolAddress((void**)&pinh,    g_inh);
    cudaGetSymbolAddress((void**)&pxth,    g_xth);
    cudaGetSymbolAddress((void**)&patt0h,  g_att0h);
    cudaGetSymbolAddress((void**)&pnhh,    g_nhh);
    cudaGetSymbolAddress((void**)&pthh,    g_thh);
    cudaGetSymbolAddress((void**)&phh2,    g_hh2);
    cudaGetSymbolAddress((void**)&phhp,    g_hhp);
    cudaGetSymbolAddress((void**)&pscore,  g_score);
    cudaGetSymbolAddress((void**)&pscorep, g_scorep);
    cudaGetSymbolAddress((void**)&psums,   g_sums);
    cudaGetSymbolAddress((void**)&pnh,     g_nh);

    static bool attr_done = false;
    const int smemS = 3 * (128 + 128) * 32 * 4;   // 98304
    const int smemH = 3 * (128 + 64)  * 32 * 4;   // 73728
    if (!attr_done) {
        cudaFuncSetAttribute(gemm_f16s,     cudaFuncAttributeMaxDynamicSharedMemorySize, smemS);
        cudaFuncSetAttribute(gemm_f16h<64>, cudaFuncAttributeMaxDynamicSharedMemorySize, smemH);
        cudaFuncSetAttribute(gemm_f16s,
                             cudaFuncAttributePreferredSharedMemoryCarveout, 100);
        cudaFuncSetAttribute(gemm_f16h<64>,
                             cudaFuncAttributePreferredSharedMemoryCarveout, 100);
        attr_done = true;
    }

    cudaStream_t s0 = 0;
    cudaStream_t s1 = g_async.s1;
    dim3 blk(256);
    const size_t wst = (size_t)G4_ * R_;
    const __half2* atth2 = reinterpret_cast<const __half2*>(patth);

    auto CV = [&](const float* src, __half* dst, size_t n, cudaStream_t st) {
        int n4 = (int)(n / 4);
        conv_half<<<(n4 + 511) / 512, blk, 0, st>>>(
            reinterpret_cast<const float4*>(src),
            reinterpret_cast<__half2*>(dst), n4);
    };

    // Fork: gate/proj weight conversions on s1, hidden under the logits GEMM
    cudaEventRecord(g_async.evFork, s0);
    cudaStreamWaitEvent(s1, g_async.evFork, 0);
    CV(i2h_w,  pi2hwh,  (size_t)L_ * P_ * G4_ * R_, s1);
    CV(h2h_w,  ph2hwh,  (size_t)L_ * P_ * G4_ * R_, s1);
    CV(a2h_w,  pa2hwh,  (size_t)L_ * P_ * G4_ * R_, s1);
    CV(proj_w, pprojwh, (size_t)V_ * R_,            s1);
    cudaEventRecord(g_async.evConv, s1);

    // s0: conversions needed by the logits chain
    CV(att,    patth,   (size_t)B_ * A_ * R_,  s0);
    CV(a2a_w,  pa2awh,  (size_t)KC_ * R_,      s0);
    CV(h2a_w,  ph2awh,  (size_t)L_ * 2 * A_ * R_, s0);
    CV(inputs + (size_t)B_ * R_,     pinh,                   (size_t)B_ * R_, s0);
    CV(inputs + (size_t)3 * B_ * R_, pinh + (size_t)B_ * R_, (size_t)B_ * R_, s0);
    CV(x,      pxth,    (size_t)B_ * R_, s0);

    // 1) hh2 for call0 of both layers (z = layer), f16
    gemm_f16h<64><<<dim3(4, 2, 2), blk, smemH, s0>>>(
        pinh, pinh, pinh, ph2awh, ph2awh, ph2awh, phh2, h2a_b,
        A_, R_, A_,
        (long long)B_ * R_, (long long)2 * A_ * R_,
        (long long)BA_, (long long)2 * A_);

    // 2) merged f16 logits GEMM: fused score (calls 0,2) + logits out (1,3)
    gemm_f16s<<<dim3(2, BA_ / 128, 4), blk, smemS, s0>>>(
        patth, pa2awh, a2a_b, phh2, d2d_w, pMh, pscorep);

    // 3) att_res0 for both layers (half output for gate GEMM)
    wsum2_sm<<<dim3(R_ / 256, B_), dim3(128), 0, s0>>>(atth2, pscorep, d2d_b, patt0h);

    // Join: gate weights must be converted before the first gate GEMM
    cudaStreamWaitEvent(s0, g_async.evConv, 0);

    for (int i = 0; i < L_; i++) {
        const float* prev_c = inputs + (size_t)(2 * i) * B_ * R_;
        const int c1 = 2 * i + 1;

        if (i == 1) {
            addconv<<<(B_ * R_) / 4 / 256, blk, 0, s0>>>(
                reinterpret_cast<const float4*>(x),
                reinterpret_cast<const float4*>(out + (size_t)1 * B_ * R_),
                reinterpret_cast<__half2*>(pxth));
        }

        // fused gate GEMM (f16): K=1536, A segs [xt, prev_h, att0_i]
        gemm_f16h<64><<<dim3(32, 2, P_), blk, smemH, s0>>>(
            pxth, pinh + (size_t)i * B_ * R_, patt0h + (size_t)i * B_ * R_,
            pi2hwh + (size_t)i * P_ * wst,
            ph2hwh + (size_t)i * P_ * wst,
            pa2hwh + (size_t)i * P_ * wst,
            psums, nullptr,
            G4_, 3 * R_, G4_,
            0, (long long)wst, (long long)B_ * G4_, 0);

        gate_kernel<<<(B_ * R_) / 256, blk, 0, s0>>>(
            psums,
            i2h_b + (size_t)i * P_ * G4_,
            h2h_b + (size_t)i * P_ * G4_,
            a2h_b + (size_t)i * P_ * G4_,
            prev_c,
            out + (size_t)(2 * i) * B_ * R_, pnh, pnhh);

        // call1 hh: K-split x4 into partials (z = k-slice of 128 halves)
        {
            const __half* bw = ph2awh + (size_t)c1 * A_ * R_;
            gemm_f16h<64><<<dim3(4, 2, 4), blk, smemH, s0>>>(
                pnhh, pnhh, pnhh, bw, bw, bw, phhp, nullptr,
                A_, 128, A_,
                128, 128, (long long)BA_, 0);
        }
        score4_kernel<<<BA_ / 8, blk, 0, s0>>>(pMh, phhp, h2a_b + (size_t)c1 * A_,
                                               d2d_w + (size_t)c1 * A_, d2d_b + c1,
                                               pscore, c1 * A_);
        wsum_sm<<<dim3(R_ / 256, B_), dim3(128), 0, s0>>>(
            atth2, pscore, pnh, out + (size_t)(2 * i + 1) * B_ * R_,
            (i == 1) ? pthh : (__half*)nullptr);
    }

    // projection (f16) + log-softmax
    gemm_f16h<64><<<dim3((V_ + 63) / 64, 2, 1), blk, smemH, s0>>>(
        pthh, pthh, pthh, pprojwh, pprojwh, pprojwh,
        out + (size_t)4 * B_ * R_, proj_b,
        V_, R_, V_, 0, 0, 0, 0);
    logsoftmax_kernel<<<B_, blk, 0, s0>>>(out + (size_t)4 * B_ * R_);
}

// round 13
// speedup vs baseline: 1.1178x; 1.0200x over previous
#include <cuda_runtime.h>
#include <cuda_fp16.h>
#include <math.h>
#include <stdint.h>

// Problem constants
#define L_   2
#define P_   3
#define R_   512
#define A_   196
#define V_   9487
#define B_   256
#define BA_  (B_*A_)        // 50176
#define KC_  (2*L_*A_)      // 784
#define G4_  (4*R_)         // 2048

// ---------------------------------------------------------------------------
// Static device scratch (allocation-free)
// ---------------------------------------------------------------------------
__device__ __half gMh    [(size_t)BA_ * KC_];     // logits half (calls 1,3 cols)
__device__ __half g_atth [(size_t)B_ * A_ * R_];  // att half
__device__ __half g_a2awh[(size_t)KC_ * R_];
__device__ __half g_i2hwh[(size_t)L_ * P_ * G4_ * R_];
__device__ __half g_h2hwh[(size_t)L_ * P_ * G4_ * R_];
__device__ __half g_a2hwh[(size_t)L_ * P_ * G4_ * R_];
__device__ __half g_h2awh[(size_t)L_ * 2 * A_ * R_];
__device__ __half g_projwh[(size_t)V_ * R_];
__device__ __half g_inh  [2 * B_ * R_];
__device__ __half g_xth  [B_ * R_];
__device__ __half g_att0h[2 * B_ * R_];
__device__ __half g_nhh  [B_ * R_];
__device__ __half g_thh  [B_ * R_];
__device__ float g_hh2  [2 * B_ * A_];
__device__ float g_hhp  [4 * B_ * A_];
__device__ float g_score[BA_];
__device__ float g_scorep[4 * BA_];
__device__ float g_sums [P_ * B_ * G4_];
__device__ float g_nh   [B_ * R_];

// ---------------------------------------------------------------------------
// Streams/events
// ---------------------------------------------------------------------------
struct AsyncCtx {
    cudaStream_t s1;
    cudaEvent_t evFork, evConv, evOdd;
    AsyncCtx() {
        cudaStreamCreateWithFlags(&s1, cudaStreamNonBlocking);
        cudaEventCreateWithFlags(&evFork, cudaEventDisableTiming);
        cudaEventCreateWithFlags(&evConv, cudaEventDisableTiming);
        cudaEventCreateWithFlags(&evOdd,  cudaEventDisableTiming);
    }
};
static AsyncCtx g_async;

// ---------------------------------------------------------------------------
// MUFU-based activations
// ---------------------------------------------------------------------------
__device__ __forceinline__ float mexp(float x) {
    float r;
    asm("ex2.approx.f32 %0, %1;" : "=f"(r) : "f"(x * 1.4426950408889634f));
    return r;
}
__device__ __forceinline__ float msig(float x) {
    float t = fminf(-1.4426950408889634f * x, 126.0f);
    float u;
    asm("ex2.approx.f32 %0, %1;" : "=f"(u) : "f"(t));
    float d = 1.0f + u;
    float r;
    asm("rcp.approx.f32 %0, %1;" : "=f"(r) : "f"(d));
    r = r * fmaf(-d, r, 2.0f);
    return r;
}
__device__ __forceinline__ float mtanh(float x) {
    return fmaf(2.0f, msig(2.0f * x), -1.0f);
}
__device__ __forceinline__ __half2 htanh2(__half2 v) {
    uint32_t vi = *reinterpret_cast<uint32_t*>(&v);
    uint32_t to;
    asm("tanh.approx.f16x2 %0, %1;" : "=r"(to) : "r"(vi));
    return *reinterpret_cast<__half2*>(&to);
}

// ---------------------------------------------------------------------------
// mma / cp.async / ldmatrix helpers
// ---------------------------------------------------------------------------
#define MMA_F16(c, a, b0, b1) \
    asm volatile("mma.sync.aligned.m16n8k16.row.col.f32.f16.f16.f32 " \
        "{%0,%1,%2,%3}, {%4,%5,%6,%7}, {%8,%9}, {%0,%1,%2,%3};" \
        : "+f"((c)[0]), "+f"((c)[1]), "+f"((c)[2]), "+f"((c)[3]) \
        : "r"((a)[0]), "r"((a)[1]), "r"((a)[2]), "r"((a)[3]), \
          "r"(b0), "r"(b1))

#define LDSM_X4(r0, r1, r2, r3, addr) \
    asm volatile("ldmatrix.sync.aligned.m8n8.x4.shared.b16 {%0,%1,%2,%3}, [%4];" \
        : "=r"(r0), "=r"(r1), "=r"(r2), "=r"(r3) : "r"(addr))

__device__ __forceinline__ uint32_t smem_u32(const void* p) {
    uint32_t a;
    asm("{ .reg .u64 t; cvta.to.shared.u64 t, %1; cvt.u32.u64 %0, t; }" : "=r"(a) : "l"(p));
    return a;
}
__device__ __forceinline__ void cp16(uint32_t dst, const void* src) {
    asm volatile("cp.async.cg.shared.global [%0], [%1], 16;" :: "r"(dst), "l"(src));
}
#define CP_COMMIT() asm volatile("cp.async.commit_group;" ::: "memory")
#define CP_WAIT1()  asm volatile("cp.async.wait_group 1;" ::: "memory")

// ---------------------------------------------------------------------------
// Generic f16 NT GEMM, fp32 out (unchanged)
// ---------------------------------------------------------------------------
template<int BN>
__global__ __launch_bounds__(256, 2)
void gemm_f16h(const __half* __restrict__ A0, const __half* __restrict__ A1,
               const __half* __restrict__ A2,
               const __half* __restrict__ B0, const __half* __restrict__ B1,
               const __half* __restrict__ B2,
               float* __restrict__ C, const float* __restrict__ bias,
               int N, int Ktot, int ldc,
               long long sA, long long sB, long long sC, long long sBias)
{
    constexpr int NT    = BN / 16;
    constexpr int AWu   = 128 * 32;
    constexpr int BWu   = BN * 32;
    constexpr int STAGE = AWu + BWu;

    extern __shared__ uint32_t smu[];

    const int tid   = threadIdx.x;
    const int warp  = tid >> 5;
    const int lane  = tid & 31;
    const int gid   = lane >> 2;
    const int tig   = lane & 3;
    const int mbase = (warp & 3) * 32;
    const int nbase = (warp >> 2) * (BN / 2);

    const int row0 = blockIdx.y * 128;
    const int col0 = blockIdx.x * BN;
    const int z    = blockIdx.z;

    const int sr  = tid >> 3;
    const int sc8 = tid & 7;
    const uint32_t smbase = smem_u32(smu);
    const uint32_t swoff  = (uint32_t)((sc8 ^ (sr & 7)) << 2);

    const int l15  = lane & 15;
    const int gAhi = lane >> 4;
    const int rB   = (lane & 7) + ((lane & 16) >> 1);
    const int gBlo = (lane >> 3) & 1;

    const int ncc = Ktot >> 6;

    auto issue = [&](int cc) {
        if (cc < ncc) {
            const int kb  = cc << 6;
            const int seg = kb >> 9;
            const int kbl = kb & 511;
            const __half* Ap = ((seg == 0) ? A0 : (seg == 1) ? A1 : A2)
                               + (long long)z * sA + kbl + sc8 * 8;
            const __half* Bp = ((seg == 0) ? B0 : (seg == 1) ? B1 : B2)
                               + (long long)z * sB + kbl + sc8 * 8;
            const uint32_t stA = smbase + (uint32_t)(cc % 3) * (STAGE * 4);
            const uint32_t stB = stA + AWu * 4;
            #pragma unroll
            for (int j = 0; j < 4; j++) {
                int r = sr + j * 32;
                cp16(stA + (r * 32) * 4 + swoff * 4,
                     Ap + (long long)(row0 + r) * 512);
            }
            #pragma unroll
            for (int j = 0; j < BN / 32; j++) {
                int r = sr + j * 32;
                int n = col0 + r; if (n >= N) n = N - 1;
                cp16(stB + (r * 32) * 4 + swoff * 4,
                     Bp + (long long)n * 512);
            }
        }
        CP_COMMIT();
    };

    float acc[2][NT][4];
    #pragma unroll
    for (int mt = 0; mt < 2; mt++)
        #pragma unroll
        for (int nt = 0; nt < NT; nt++)
            #pragma unroll
            for (int q = 0; q < 4; q++) acc[mt][nt][q] = 0.f;

    issue(0);
    issue(1);

    for (int cc = 0; cc < ncc; cc++) {
        CP_WAIT1();
        __syncthreads();
        issue(cc + 2);

        const uint32_t stA = smbase + (uint32_t)(cc % 3) * (STAGE * 4);
        const uint32_t stB = stA + AWu * 4;

        #pragma unroll
        for (int ks = 0; ks < 4; ks++) {
            uint32_t aF[2][4];
            #pragma unroll
            for (int mt = 0; mt < 2; mt++) {
                const int rA = mbase + mt * 16 + l15;
                const uint32_t g = (uint32_t)((2 * ks + gAhi) ^ (rA & 7));
                LDSM_X4(aF[mt][0], aF[mt][1], aF[mt][2], aF[mt][3],
                        stA + (uint32_t)rA * 128 + (g << 4));
            }
            #pragma unroll
            for (int p = 0; p < BN / 32; p++) {
                const int rBB = nbase + p * 16 + rB;
                const uint32_t g = (uint32_t)((2 * ks + gBlo) ^ (rBB & 7));
                uint32_t b0, b1, b2, b3;
                LDSM_X4(b0, b1, b2, b3, stB + (uint32_t)rBB * 128 + (g << 4));
                MMA_F16(acc[0][2 * p],     aF[0], b0, b1);
                MMA_F16(acc[1][2 * p],     aF[1], b0, b1);
                MMA_F16(acc[0][2 * p + 1], aF[0], b2, b3);
                MMA_F16(acc[1][2 * p + 1], aF[1], b2, b3);
            }
        }
    }

    float* Cz = C + (long long)z * sC;
    const float* bz = bias ? (bias + (long long)z * sBias) : nullptr;
    const bool even = ((ldc & 1) == 0);
    #pragma unroll
    for (int mt = 0; mt < 2; mt++) {
        const int rlo = row0 + mbase + mt * 16 + gid;
        const int rhi = rlo + 8;
        #pragma unroll
        for (int nt = 0; nt < NT; nt++) {
            const int n0 = col0 + nbase + nt * 8 + 2 * tig;
            if (n0 >= N) continue;
            float b0v = bz ? bz[n0] : 0.f;
            float b1v = (bz && n0 + 1 < N) ? bz[n0 + 1] : 0.f;
            float c0 = acc[mt][nt][0] + b0v;
            float c1 = acc[mt][nt][1] + b1v;
            float c2 = acc[mt][nt][2] + b0v;
            float c3 = acc[mt][nt][3] + b1v;
            if (even && (n0 + 1 < N)) {
                *reinterpret_cast<float2*>(Cz + (long long)rlo * ldc + n0) = make_float2(c0, c1);
                *reinterpret_cast<float2*>(Cz + (long long)rhi * ldc + n0) = make_float2(c2, c3);
            } else {
                Cz[(long long)rlo * ldc + n0] = c0;
                Cz[(long long)rhi * ldc + n0] = c2;
                if (n0 + 1 < N) {
                    Cz[(long long)rlo * ldc + n0 + 1] = c1;
                    Cz[(long long)rhi * ldc + n0 + 1] = c3;
                }
            }
        }
    }
}

// ---------------------------------------------------------------------------
// Logits GEMM split by call parity. ODD=0: fused score (calls 0,2).
// ODD=1: half logits into gMh (calls 1,3). grid (2, BA_/128, 2).
// ---------------------------------------------------------------------------
template<int ODD>
__global__ __launch_bounds__(256, 2)
void gemm_f16s(const __half* __restrict__ Ah, const __half* __restrict__ BhAll,
               const float* __restrict__ biasAll, const float* __restrict__ hh2,
               const float* __restrict__ wAll,
               __half* __restrict__ Mout, float* __restrict__ scorep)
{
    constexpr int AW    = 128 * 32;
    constexpr int STAGE = AW + AW;

    extern __shared__ uint32_t smu[];
    __shared__ float sred[128];

    const int tid   = threadIdx.x;
    const int warp  = tid >> 5;
    const int lane  = tid & 31;
    const int gid   = lane >> 2;
    const int tig   = lane & 3;
    const int mbase = (warp & 3) * 32;
    const int nbase = (warp >> 2) * 64;

    const int row0 = blockIdx.y * 128;
    const int col0 = blockIdx.x * 128;
    const int zl   = blockIdx.z;             // layer
    const int call = ODD + 2 * zl;

    const __half* Bz = BhAll + (size_t)call * A_ * R_;

    const int sr  = tid >> 3;
    const int sc8 = tid & 7;
    const uint32_t smbase = smem_u32(smu);
    const uint32_t swoff  = (uint32_t)((sc8 ^ (sr & 7)) << 2);

    if (ODD == 0 && tid < 128) sred[tid] = 0.f;

    const int l15  = lane & 15;
    const int gAhi = lane >> 4;
    const int rB   = (lane & 7) + ((lane & 16) >> 1);
    const int gBlo = (lane >> 3) & 1;

    auto issue = [&](int cc) {
        if (cc < 8) {
            const int kb = cc * 64;
            const uint32_t stA = smbase + (uint32_t)(cc % 3) * (STAGE * 4);
            const uint32_t stB = stA + AW * 4;
            #pragma unroll
            for (int j = 0; j < 4; j++) {
                int r = sr + j * 32;
                cp16(stA + (r * 32) * 4 + swoff * 4,
                     Ah + (long long)(row0 + r) * 512 + kb + sc8 * 8);
                int n = col0 + r; if (n >= A_) n = A_ - 1;
                cp16(stB + (r * 32) * 4 + swoff * 4,
                     Bz + (long long)n * 512 + kb + sc8 * 8);
            }
        }
        CP_COMMIT();
    };

    float acc[2][8][4];
    #pragma unroll
    for (int mt = 0; mt < 2; mt++)
        #pragma unroll
        for (int nt = 0; nt < 8; nt++)
            #pragma unroll
            for (int q = 0; q < 4; q++) acc[mt][nt][q] = 0.f;

    issue(0);
    issue(1);

    for (int cc = 0; cc < 8; cc++) {
        CP_WAIT1();
        __syncthreads();
        issue(cc + 2);

        const uint32_t stA = smbase + (uint32_t)(cc % 3) * (STAGE * 4);
        const uint32_t stB = stA + AW * 4;

        #pragma unroll
        for (int ks = 0; ks < 4; ks++) {
            uint32_t aF[2][4];
            #pragma unroll
            for (int mt = 0; mt < 2; mt++) {
                const int rA = mbase + mt * 16 + l15;
                const uint32_t g = (uint32_t)((2 * ks + gAhi) ^ (rA & 7));
                LDSM_X4(aF[mt][0], aF[mt][1], aF[mt][2], aF[mt][3],
                        stA + (uint32_t)rA * 128 + (g << 4));
            }
            #pragma unroll
            for (int p = 0; p < 4; p++) {
                const int rBB = nbase + p * 16 + rB;
                const uint32_t g = (uint32_t)((2 * ks + gBlo) ^ (rBB & 7));
                uint32_t b0, b1, b2, b3;
                LDSM_X4(b0, b1, b2, b3, stB + (uint32_t)rBB * 128 + (g << 4));
                MMA_F16(acc[0][2 * p],     aF[0], b0, b1);
                MMA_F16(acc[1][2 * p],     aF[1], b0, b1);
                MMA_F16(acc[0][2 * p + 1], aF[0], b2, b3);
                MMA_F16(acc[1][2 * p + 1], aF[1], b2, b3);
            }
        }
    }

    const float* bz = biasAll + (size_t)call * A_;

    if (ODD) {
        __half* Cz = Mout;
        #pragma unroll
        for (int mt = 0; mt < 2; mt++) {
            const int rlo = row0 + mbase + mt * 16 + gid;
            const int rhi = rlo + 8;
            #pragma unroll
            for (int nt = 0; nt < 8; nt++) {
                const int n0 = col0 + nbase + nt * 8 + 2 * tig;
                if (n0 >= A_) continue;
                float b0v = bz[n0], b1v = bz[n0 + 1];
                *reinterpret_cast<__half2*>(Cz + (long long)rlo * KC_ + call * A_ + n0) =
                    __floats2half2_rn(acc[mt][nt][0] + b0v, acc[mt][nt][1] + b1v);
                *reinterpret_cast<__half2*>(Cz + (long long)rhi * KC_ + call * A_ + n0) =
                    __floats2half2_rn(acc[mt][nt][2] + b0v, acc[mt][nt][3] + b1v);
            }
        }
    } else {
        const float* hz = hh2 + (size_t)zl * BA_;
        const float* wz = wAll + (size_t)call * A_;
        __syncthreads();
        #pragma unroll
        for (int mt = 0; mt < 2; mt++) {
            const int rlo = row0 + mbase + mt * 16 + gid;
            const int rhi = rlo + 8;
            const float hl = hz[rlo], hb = hz[rhi];
            float plo = 0.f, phi = 0.f;
            #pragma unroll
            for (int nt = 0; nt < 8; nt++) {
                const int n0 = col0 + nbase + nt * 8 + 2 * tig;
                if (n0 >= A_) continue;
                const float b0v = bz[n0], b1v = bz[n0 + 1];
                const float w0v = wz[n0], w1v = wz[n0 + 1];
                float2 tl = __half22float2(htanh2(__floats2half2_rn(
                    acc[mt][nt][0] + b0v + hl, acc[mt][nt][1] + b1v + hl)));
                float2 th = __half22float2(htanh2(__floats2half2_rn(
                    acc[mt][nt][2] + b0v + hb, acc[mt][nt][3] + b1v + hb)));
                plo = fmaf(tl.x, w0v, fmaf(tl.y, w1v, plo));
                phi = fmaf(th.x, w0v, fmaf(th.y, w1v, phi));
            }
            plo += __shfl_xor_sync(0xFFFFFFFFu, plo, 1);
            plo += __shfl_xor_sync(0xFFFFFFFFu, plo, 2);
            phi += __shfl_xor_sync(0xFFFFFFFFu, phi, 1);
            phi += __shfl_xor_sync(0xFFFFFFFFu, phi, 2);
            if (tig == 0) {
                atomicAdd(&sred[mbase + mt * 16 + gid], plo);
                atomicAdd(&sred[mbase + mt * 16 + gid + 8], phi);
            }
        }
        __syncthreads();
        if (tid < 128)
            scorep[(size_t)(zl * 2 + blockIdx.x) * BA_ + row0 + tid] = sred[tid];
    }
}

// ---------------------------------------------------------------------------
// fp32 -> half conversion (2 float4 per thread)
// ---------------------------------------------------------------------------
__global__ __launch_bounds__(256)
void conv_half(const float4* __restrict__ in, __half2* __restrict__ outp, int n4)
{
    const int i0 = blockIdx.x * 512 + threadIdx.x;
    const int i1 = i0 + 256;
    if (i0 < n4) {
        float4 v = in[i0];
        outp[2 * i0]     = __floats2half2_rn(v.x, v.y);
        outp[2 * i0 + 1] = __floats2half2_rn(v.z, v.w);
    }
    if (i1 < n4) {
        float4 v = in[i1];
        outp[2 * i1]     = __floats2half2_rn(v.x, v.y);
        outp[2 * i1 + 1] = __floats2half2_rn(v.z, v.w);
    }
}

// o = half(a + b)
__global__ __launch_bounds__(256)
void addconv(const float4* __restrict__ a, const float4* __restrict__ b,
             __half2* __restrict__ o)
{
    const int i = blockIdx.x * 256 + threadIdx.x;
    float4 va = a[i], vb = b[i];
    o[2 * i]     = __floats2half2_rn(va.x + vb.x, va.y + vb.y);
    o[2 * i + 1] = __floats2half2_rn(va.z + vb.z, va.w + vb.w);
}

// ---------------------------------------------------------------------------
// Score from 4 K-split hh partials + per-a bias (calls 1,3)
// ---------------------------------------------------------------------------
__global__ __launch_bounds__(256)
void score4_kernel(const __half* __restrict__ Mh, const float* __restrict__ hhp,
                   const float* __restrict__ hbias,
                   const float* __restrict__ w, const float* __restrict__ d2db,
                   float* __restrict__ score, int col_off)
{
    const int id   = blockIdx.x * 8 + (threadIdx.x >> 5);
    const int lane = threadIdx.x & 31;
    const float h  = hhp[id] + hhp[BA_ + id] + hhp[2 * BA_ + id] + hhp[3 * BA_ + id]
                   + hbias[id % A_];
    const __half2* row = reinterpret_cast<const __half2*>(
        Mh + (size_t)id * KC_ + col_off);
    const float2* w2 = reinterpret_cast<const float2*>(w);
    const __half2 h2 = __float2half2_rn(h);
    float s = 0.f;
    for (int k = lane; k < A_ / 2; k += 32) {
        float2 tf = __half22float2(htanh2(__hadd2(row[k], h2)));
        float2 ww = w2[k];
        s = fmaf(tf.x, ww.x, s);
        s = fmaf(tf.y, ww.y, s);
    }
    #pragma unroll
    for (int o = 16; o > 0; o >>= 1)
        s += __shfl_xor_sync(0xFFFFFFFFu, s, o);
    if (lane == 0) score[id] = s + d2db[0];
}

// ---------------------------------------------------------------------------
// Softmax helper from explicit logit values
// ---------------------------------------------------------------------------
__device__ __forceinline__ void softmax_vals(float l0, float l1, float* sw,
                                             float* red, int tid)
{
    const int t2 = tid + 128;
    red[tid] = fmaxf(l0, l1); __syncthreads();
    for (int s = 64; s > 0; s >>= 1) {
        if (tid < s) red[tid] = fmaxf(red[tid], red[tid + s]);
        __syncthreads();
    }
    const float mx = red[0]; __syncthreads();
    float e0 = mexp(l0 - mx);
    float e1 = (t2 < A_) ? mexp(l1 - mx) : 0.f;
    red[tid] = e0 + e1; __syncthreads();
    for (int s = 64; s > 0; s >>= 1) {
        if (tid < s) red[tid] += red[tid + s];
        __syncthreads();
    }
    const float inv = 1.f / red[0];
    sw[tid] = e0 * inv;
    if (t2 < A_) sw[t2] = e1 * inv;
    __syncthreads();
}

// ---------------------------------------------------------------------------
// Dual weighted sum from fused-score partials (calls 0,2) -> HALF att0
// ---------------------------------------------------------------------------
__global__ __launch_bounds__(128)
void wsum2_sm(const __half2* __restrict__ atth, const float* __restrict__ sp,
              const float* __restrict__ d2db, __half* __restrict__ outp)
{
    const int b   = blockIdx.y;
    const int tid = threadIdx.x;
    __shared__ float w0[A_], w1[A_];
    __shared__ float red[128];

    const int i0 = b * A_ + tid;
    const int i1 = i0 + 128;
    const bool v1 = (tid + 128) < A_;
    {
        float db = d2db[0];
        float l0 = sp[i0] + sp[BA_ + i0] + db;
        float l1 = v1 ? (sp[i1] + sp[BA_ + i1] + db) : -INFINITY;
        softmax_vals(l0, l1, w0, red, tid);
    }
    {
        float db = d2db[2];
        float l0 = sp[2 * BA_ + i0] + sp[3 * BA_ + i0] + db;
        float l1 = v1 ? (sp[2 * BA_ + i1] + sp[3 * BA_ + i1] + db) : -INFINITY;
        softmax_vals(l0, l1, w1, red, tid);
    }

    const __half2* ab = atth + (((size_t)b * A_ * R_) >> 1)
                       + (blockIdx.x * 256 >> 1) + tid;
    float ax = 0.f, ay = 0.f, bx = 0.f, by = 0.f;
    #pragma unroll 14
    for (int a = 0; a < A_; a++) {
        float2 f = __half22float2(ab[a * (R_ / 2)]);
        ax = fmaf(f.x, w0[a], ax); ay = fmaf(f.y, w0[a], ay);
        bx = fmaf(f.x, w1[a], bx); by = fmaf(f.y, w1[a], by);
    }
    const int r = blockIdx.x * 256 + tid * 2;
    *reinterpret_cast<__half2*>(outp + b * R_ + r)           = __floats2half2_rn(ax, ay);
    *reinterpret_cast<__half2*>(outp + B_ * R_ + b * R_ + r) = __floats2half2_rn(bx, by);
}

// Single weighted sum + softmax (+ addv); optional half copy of the output
__global__ __launch_bounds__(128)
void wsum_sm(const __half2* __restrict__ atth, const float* __restrict__ score,
             const float* __restrict__ addv, float* __restrict__ outp,
             __half* __restrict__ outh)
{
    const int b   = blockIdx.y;
    const int tid = threadIdx.x;
    __shared__ float w0[A_];
    __shared__ float red[128];

    const float* sc = score + b * A_;
    float l0 = sc[tid];
    float l1 = (tid + 128 < A_) ? sc[tid + 128] : -INFINITY;
    softmax_vals(l0, l1, w0, red, tid);

    const __half2* ab = atth + (((size_t)b * A_ * R_) >> 1)
                       + (blockIdx.x * 256 >> 1) + tid;
    float ax = 0.f, ay = 0.f;
    #pragma unroll 14
    for (int a = 0; a < A_; a++) {
        float2 f = __half22float2(ab[a * (R_ / 2)]);
        ax = fmaf(f.x, w0[a], ax);
        ay = fmaf(f.y, w0[a], ay);
    }
    const int r = blockIdx.x * 256 + tid * 2;
    float2 av = *reinterpret_cast<const float2*>(addv + b * R_ + r);
    ax += av.x; ay += av.y;
    *reinterpret_cast<float2*>(outp + b * R_ + r) = make_float2(ax, ay);
    if (outh)
        *reinterpret_cast<__half2*>(outh + b * R_ + r) = __floats2half2_rn(ax, ay);
}

// ---------------------------------------------------------------------------
// Gates + cell update + mean over P (float + half next_h outputs)
// ---------------------------------------------------------------------------
__global__ __launch_bounds__(256)
void gate_kernel(const float* __restrict__ sums,
                 const float* __restrict__ bi, const float* __restrict__ bh,
                 const float* __restrict__ ba,
                 const float* __restrict__ prev_c,
                 float* __restrict__ next_c, float* __restrict__ next_h,
                 __half* __restrict__ next_hh)
{
    const int idx = blockIdx.x * 256 + threadIdx.x;
    const int b = idx >> 9, r = idx & (R_ - 1);
    const float pc = prev_c[idx];
    float ca = 0.f, ha = 0.f;
    #pragma unroll
    for (int p = 0; p < P_; p++) {
        const long long base = ((long long)p * B_ + b) * G4_;
        const int bb = p * G4_;
        float si = sums[base + r]        + bi[bb + r]        + bh[bb + r]        + ba[bb + r];
        float sf = sums[base + R_ + r]   + bi[bb + R_ + r]   + bh[bb + R_ + r]   + ba[bb + R_ + r];
        float so = sums[base + 2*R_ + r] + bi[bb + 2*R_ + r] + bh[bb + 2*R_ + r] + ba[bb + 2*R_ + r];
        float st = sums[base + 3*R_ + r] + bi[bb + 3*R_ + r] + bh[bb + 3*R_ + r] + ba[bb + 3*R_ + r];
        float ig = msig(si);
        float fg = msig(sf);
        float og = msig(so);
        float it = mtanh(st);
        float nc = fg * pc + ig * it;
        ca += nc;
        ha += og * mtanh(nc);
    }
    const float hval = ha * (1.f / 3.f);
    next_c[idx]  = ca * (1.f / 3.f);
    next_h[idx]  = hval;
    next_hh[idx] = __float2half(hval);
}

// ---------------------------------------------------------------------------
// In-place log-softmax over V per row
// ---------------------------------------------------------------------------
__global__ __launch_bounds__(256)
void logsoftmax_kernel(float* __restrict__ x)
{
    const int b = blockIdx.x, tid = threadIdx.x;
    __shared__ float red[256];
    float* row = x + (long long)b * V_;

    float mx = -INFINITY;
    for (int i = tid; i < V_; i += 256) mx = fmaxf(mx, row[i]);
    red[tid] = mx; __syncthreads();
    for (int s = 128; s > 0; s >>= 1) {
        if (tid < s) red[tid] = fmaxf(red[tid], red[tid + s]);
        __syncthreads();
    }
    mx = red[0]; __syncthreads();

    float sum = 0.f;
    for (int i = tid; i < V_; i += 256) sum += mexp(row[i] - mx);
    red[tid] = sum; __syncthreads();
    for (int s = 128; s > 0; s >>= 1) {
        if (tid < s) red[tid] += red[tid + s];
        __syncthreads();
    }
    const float lz = logf(red[0]) + mx;
    for (int i = tid; i < V_; i += 256) row[i] = row[i] - lz;
}

// ---------------------------------------------------------------------------
// Host launch
// ---------------------------------------------------------------------------
extern "C" void kernel_launch(void* const* d_in, const int* in_sizes, int n_in,
                              void* d_out, int out_size)
{
    (void)in_sizes; (void)n_in; (void)out_size;
    const float* x      = (const float*)d_in[0];
    const float* att    = (const float*)d_in[1];
    const float* inputs = (const float*)d_in[2];
    const float* i2h_w  = (const float*)d_in[3];
    const float* i2h_b  = (const float*)d_in[4];
    const float* h2h_w  = (const float*)d_in[5];
    const float* h2h_b  = (const float*)d_in[6];
    const float* a2h_w  = (const float*)d_in[7];
    const float* a2h_b  = (const float*)d_in[8];
    const float* a2a_w  = (const float*)d_in[9];
    const float* a2a_b  = (const float*)d_in[10];
    const float* h2a_w  = (const float*)d_in[11];
    const float* h2a_b  = (const float*)d_in[12];
    const float* d2d_w  = (const float*)d_in[13];
    const float* d2d_b  = (const float*)d_in[14];
    const float* proj_w = (const float*)d_in[15];
    const float* proj_b = (const float*)d_in[16];
    float* out = (float*)d_out;

    __half *pMh, *patth, *pa2awh, *pi2hwh, *ph2hwh, *pa2hwh, *ph2awh, *pprojwh;
    __half *pinh, *pxth, *patt0h, *pnhh, *pthh;
    float *phh2, *phhp, *pscore, *pscorep, *psums, *pnh;
    cudaGetSymbolAddress((void**)&pMh,     gMh);
    cudaGetSymbolAddress((void**)&patth,   g_atth);
    cudaGetSymbolAddress((void**)&pa2awh,  g_a2awh);
    cudaGetSymbolAddress((void**)&pi2hwh,  g_i2hwh);
    cudaGetSymbolAddress((void**)&ph2hwh,  g_h2hwh);
    cudaGetSymbolAddress((void**)&pa2hwh,  g_a2hwh);
    cudaGetSymbolAddress((void**)&ph2awh,  g_h2awh);
    cudaGetSymbolAddress((void**)&pprojwh, g_projwh);
    cudaGetSymbolAddress((void**)&pinh,    g_inh);
    cudaGetSymbolAddress((void**)&pxth,    g_xth);
    cudaGetSymbolAddress((void**)&patt0h,  g_att0h);
    cudaGetSymbolAddress((void**)&pnhh,    g_nhh);
    cudaGetSymbolAddress((void**)&pthh,    g_thh);
    cudaGetSymbolAddress((void**)&phh2,    g_hh2);
    cudaGetSymbolAddress((void**)&phhp,    g_hhp);
    cudaGetSymbolAddress((void**)&pscore,  g_score);
    cudaGetSymbolAddress((void**)&pscorep, g_scorep);
    cudaGetSymbolAddress((void**)&psums,   g_sums);
    cudaGetSymbolAddress((void**)&pnh,     g_nh);

    static bool attr_done = false;
    const int smemS = 3 * (128 + 128) * 32 * 4;   // 98304
    const int smemH = 3 * (128 + 64)  * 32 * 4;   // 73728
    if (!attr_done) {
        cudaFuncSetAttribute(gemm_f16s<0>,  cudaFuncAttributeMaxDynamicSharedMemorySize, smemS);
        cudaFuncSetAttribute(gemm_f16s<1>,  cudaFuncAttributeMaxDynamicSharedMemorySize, smemS);
        cudaFuncSetAttribute(gemm_f16h<64>, cudaFuncAttributeMaxDynamicSharedMemorySize, smemH);
        cudaFuncSetAttribute(gemm_f16s<0>,
                             cudaFuncAttributePreferredSharedMemoryCarveout, 100);
        cudaFuncSetAttribute(gemm_f16s<1>,
                             cudaFuncAttributePreferredSharedMemoryCarveout, 100);
        cudaFuncSetAttribute(gemm_f16h<64>,
                             cudaFuncAttributePreferredSharedMemoryCarveout, 100);
        attr_done = true;
    }

    cudaStream_t s0 = 0;
    cudaStream_t s1 = g_async.s1;
    dim3 blk(256);
    const size_t wst = (size_t)G4_ * R_;
    const __half2* atth2 = reinterpret_cast<const __half2*>(patth);

    auto CV = [&](const float* src, __half* dst, size_t n, cudaStream_t st) {
        int n4 = (int)(n / 4);
        conv_half<<<(n4 + 511) / 512, blk, 0, st>>>(
            reinterpret_cast<const float4*>(src),
            reinterpret_cast<__half2*>(dst), n4);
    };

    // s0: conversions the logits GEMMs need
    CV(att,    patth,   (size_t)B_ * A_ * R_,  s0);
    CV(a2a_w,  pa2awh,  (size_t)KC_ * R_,      s0);

    // Fork s1 after att/a2aw are converted
    cudaEventRecord(g_async.evFork, s0);
    cudaStreamWaitEvent(s1, g_async.evFork, 0);

    // s1: gate/proj weight conversions, then the ODD logits GEMM (calls 1,3)
    CV(i2h_w,  pi2hwh,  (size_t)L_ * P_ * G4_ * R_, s1);
    CV(h2h_w,  ph2hwh,  (size_t)L_ * P_ * G4_ * R_, s1);
    CV(a2h_w,  pa2hwh,  (size_t)L_ * P_ * G4_ * R_, s1);
    CV(proj_w, pprojwh, (size_t)V_ * R_,            s1);
    cudaEventRecord(g_async.evConv, s1);
    gemm_f16s<1><<<dim3(2, BA_ / 128, 2), blk, smemS, s1>>>(
        patth, pa2awh, a2a_b, nullptr, nullptr, pMh, nullptr);
    cudaEventRecord(g_async.evOdd, s1);

    // s0: remaining conversions + hh2 + EVEN logits GEMM (fused score)
    CV(h2a_w,  ph2awh,  (size_t)L_ * 2 * A_ * R_, s0);
    CV(inputs + (size_t)B_ * R_,     pinh,                   (size_t)B_ * R_, s0);
    CV(inputs + (size_t)3 * B_ * R_, pinh + (size_t)B_ * R_, (size_t)B_ * R_, s0);
    CV(x,      pxth,    (size_t)B_ * R_, s0);

    gemm_f16h<64><<<dim3(4, 2, 2), blk, smemH, s0>>>(
        pinh, pinh, pinh, ph2awh, ph2awh, ph2awh, phh2, h2a_b,
        A_, R_, A_,
        (long long)B_ * R_, (long long)2 * A_ * R_,
        (long long)BA_, (long long)2 * A_);

    gemm_f16s<0><<<dim3(2, BA_ / 128, 2), blk, smemS, s0>>>(
        patth, pa2awh, a2a_b, phh2, d2d_w, nullptr, pscorep);

    // att_res0 for both layers (half output)
    wsum2_sm<<<dim3(R_ / 256, B_), dim3(128), 0, s0>>>(atth2, pscorep, d2d_b, patt0h);

    // Join: gate weights before the first gate GEMM
    cudaStreamWaitEvent(s0, g_async.evConv, 0);

    for (int i = 0; i < L_; i++) {
        const float* prev_c = inputs + (size_t)(2 * i) * B_ * R_;
        const int c1 = 2 * i + 1;

        if (i == 1) {
            addconv<<<(B_ * R_) / 4 / 256, blk, 0, s0>>>(
                reinterpret_cast<const float4*>(x),
                reinterpret_cast<const float4*>(out + (size_t)1 * B_ * R_),
                reinterpret_cast<__half2*>(pxth));
        }

        // fused gate GEMM (f16): K=1536, A segs [xt, prev_h, att0_i]
        gemm_f16h<64><<<dim3(32, 2, P_), blk, smemH, s0>>>(
            pxth, pinh + (size_t)i * B_ * R_, patt0h + (size_t)i * B_ * R_,
            pi2hwh + (size_t)i * P_ * wst,
            ph2hwh + (size_t)i * P_ * wst,
            pa2hwh + (size_t)i * P_ * wst,
            psums, nullptr,
            G4_, 3 * R_, G4_,
            0, (long long)wst, (long long)B_ * G4_, 0);

        gate_kernel<<<(B_ * R_) / 256, blk, 0, s0>>>(
            psums,
            i2h_b + (size_t)i * P_ * G4_,
            h2h_b + (size_t)i * P_ * G4_,
            a2h_b + (size_t)i * P_ * G4_,
            prev_c,
            out + (size_t)(2 * i) * B_ * R_, pnh, pnhh);

        // call1 hh: K-split x4 into partials
        {
            const __half* bw = ph2awh + (size_t)c1 * A_ * R_;
            gemm_f16h<64><<<dim3(4, 2, 4), blk, smemH, s0>>>(
                pnhh, pnhh, pnhh, bw, bw, bw, phhp, nullptr,
                A_, 128, A_,
                128, 128, (long long)BA_, 0);
        }
        if (i == 0) cudaStreamWaitEvent(s0, g_async.evOdd, 0);   // odd logits ready
        score4_kernel<<<BA_ / 8, blk, 0, s0>>>(pMh, phhp, h2a_b + (size_t)c1 * A_,
                                               d2d_w + (size_t)c1 * A_, d2d_b + c1,
                                               pscore, c1 * A_);
        wsum_sm<<<dim3(R_ / 256, B_), dim3(128), 0, s0>>>(
            atth2, pscore, pnh, out + (size_t)(2 * i + 1) * B_ * R_,
            (i == 1) ? pthh : (__half*)nullptr);
    }

    // projection (f16) + log-softmax
    gemm_f16h<64><<<dim3((V_ + 63) / 64, 2, 1), blk, smemH, s0>>>(
        pthh, pthh, pthh, pprojwh, pprojwh, pprojwh,
        out + (size_t)4 * B_ * R_, proj_b,
        V_, R_, V_, 0, 0, 0, 0);
    logsoftmax_kernel<<<B_, blk, 0, s0>>>(out + (size_t)4 * B_ * R_);
}